// round 7
// baseline (speedup 1.0000x reference)
#include <cuda_runtime.h>
#include <cuda_bf16.h>
#include <cstdint>

// ============================================================================
// out = sigmoid(YK @ XQ^T) @ YK + XQ ;  XQ = x@W1+b1, YK = y@W2+b2
// B=4, HW=4096, C=NF=128 fp32.
// mma.sync bf16 hi/lo split (hh+hl+lh). R7: 64-row i-tiles, 32-wide j-tiles,
// 128 threads/CTA, 93KB smem -> 256 CTAs, 2 independent CTAs/SM so the two
// CTAs' phases interleave and fill tensor-pipe bubbles.
// ============================================================================

constexpr int kB = 4, kHW = 4096, kC = 128;
constexpr int TJ = 32, NJ = kHW / TJ;     // 32-wide j tiles, 128 steps
constexpr int TI = 64;                    // i-tile rows (4 warps x 16)

// smem strides in b32 units (conflict-free for the frag access patterns)
constexpr int XQ_STR = 68;   // 128 bf16 + 8 pad
constexpr int YT_STR = 20;   // 32 bf16 + 8 pad

// smem byte layout: two j-tile buffers + resident YKi_lo
constexpr int XQH_OFF = 0;                      // 32 x 272 B = 8704
constexpr int XQL_OFF = 8704;
constexpr int YTH_OFF = 17408;                  // 128 x 80 B = 10240
constexpr int YTL_OFF = 27648;
constexpr int BUF_BYTES = 37888;
constexpr int YKIL_OFF = 2 * BUF_BYTES;         // 64 x 272 B = 17408
constexpr int SMEM_TOTAL = YKIL_OFF + 17408;    // 93184 B  (2 CTAs/SM fit)

// global scratch (allocation-free rule)
__device__ float          g_xq  [kB*kHW*kC];
__device__ unsigned short g_xq_h[kB*kHW*kC], g_xq_l[kB*kHW*kC];
__device__ unsigned short g_yk_h[kB*kHW*kC], g_yk_l[kB*kHW*kC];
__device__ unsigned short g_yt_h[kB*kHW*kC], g_yt_l[kB*kHW*kC];  // [b][feat][pix]

// ---------------------------------------------------------------------------
__device__ __forceinline__ uint32_t smem_u32(const void* p) {
    uint32_t a;
    asm("{ .reg .u64 t; cvta.to.shared.u64 t, %1; cvt.u32.u64 %0, t; }" : "=r"(a) : "l"(p));
    return a;
}
#define CP16(sm_addr, g_ptr) \
    asm volatile("cp.async.cg.shared.global [%0], [%1], 16;" \
        :: "r"(sm_addr), "l"(__cvta_generic_to_global(g_ptr)) : "memory")
#define CP_COMMIT() asm volatile("cp.async.commit_group;" ::: "memory")
#define CP_WAIT0()  asm volatile("cp.async.wait_group 0;" ::: "memory")

// D += A(4xb32 bf16) * B(2xb32 bf16), m16n8k16 row.col, fp32 accum
__device__ __forceinline__ void mma_bf16(float* d, const uint32_t* a,
                                         uint32_t b0, uint32_t b1) {
    asm volatile(
        "mma.sync.aligned.m16n8k16.row.col.f32.bf16.bf16.f32 "
        "{%0,%1,%2,%3}, {%4,%5,%6,%7}, {%8,%9}, {%0,%1,%2,%3};"
        : "+f"(d[0]), "+f"(d[1]), "+f"(d[2]), "+f"(d[3])
        : "r"(a[0]), "r"(a[1]), "r"(a[2]), "r"(a[3]), "r"(b0), "r"(b1));
}

// split pair (a0,a1) -> packed bf16x2 hi and lo-residual
__device__ __forceinline__ void packHL(float a0, float a1, uint32_t& hi, uint32_t& lo) {
    __nv_bfloat16 h0 = __float2bfloat16(a0), h1 = __float2bfloat16(a1);
    float l0 = a0 - __bfloat162float(h0);
    float l1 = a1 - __bfloat162float(h1);
    hi = (uint32_t)__bfloat16_as_ushort(h0) | ((uint32_t)__bfloat16_as_ushort(h1) << 16);
    asm("cvt.rn.bf16x2.f32 %0, %1, %2;" : "=r"(lo) : "f"(l1), "f"(l0));
}

// ---------------------------------------------------------------------------
// Projection: XQ/YK fp32 + bf16 hi/lo splits, plus transposed YK (g_yt).
// grid (256, 2), block 256.   (unchanged from R6)
// ---------------------------------------------------------------------------
__global__ __launch_bounds__(256) void proj_kernel(
    const float* __restrict__ x,  const float* __restrict__ y,
    const float* __restrict__ W1, const float* __restrict__ b1,
    const float* __restrict__ W2, const float* __restrict__ b2)
{
    __shared__ float  xs[64][129];
    __shared__ float4 ws[16][32];

    const int which = blockIdx.y;
    const float* in   = which ? y  : x;
    const float* W    = which ? W2 : W1;
    const float* bias = which ? b2 : b1;

    const int base = blockIdx.x * 64;
    const int t = threadIdx.x, row = t & 63, fgrp = t >> 6, f0 = fgrp * 32;

    for (int v = t; v < 64*32; v += 256) {
        int r = v >> 5, c4 = v & 31;
        float4 d = reinterpret_cast<const float4*>(in + (long)(base + r)*kC)[c4];
        xs[r][c4*4+0]=d.x; xs[r][c4*4+1]=d.y; xs[r][c4*4+2]=d.z; xs[r][c4*4+3]=d.w;
    }
    float acc[32];
    #pragma unroll
    for (int i = 0; i < 32; i++) acc[i] = bias[f0 + i];

    for (int c0 = 0; c0 < kC; c0 += 16) {
        __syncthreads();
        for (int v = t; v < 16*32; v += 256) {
            int r = v >> 5, c4 = v & 31;
            ws[r][c4] = reinterpret_cast<const float4*>(W + (long)(c0 + r)*kC)[c4];
        }
        __syncthreads();
        #pragma unroll
        for (int cc = 0; cc < 16; cc++) {
            float xv = xs[row][c0 + cc];
            #pragma unroll
            for (int q = 0; q < 8; q++) {
                float4 w = ws[cc][fgrp*8 + q];
                acc[q*4+0] += xv*w.x; acc[q*4+1] += xv*w.y;
                acc[q*4+2] += xv*w.z; acc[q*4+3] += xv*w.w;
            }
        }
    }

    const int prow = base + row;
    unsigned short hs[32], ls[32];
    #pragma unroll
    for (int i = 0; i < 32; i++) {
        float v = acc[i];
        __nv_bfloat16 h = __float2bfloat16(v);
        float lf = v - __bfloat162float(h);
        hs[i] = __bfloat16_as_ushort(h);
        ls[i] = __bfloat16_as_ushort(__float2bfloat16(lf));
    }
    unsigned hw_[16], lw_[16];
    #pragma unroll
    for (int k = 0; k < 16; k++) {
        hw_[k] = (unsigned)hs[2*k] | ((unsigned)hs[2*k+1] << 16);
        lw_[k] = (unsigned)ls[2*k] | ((unsigned)ls[2*k+1] << 16);
    }
    const int u4base = prow * 16 + fgrp * 4;

    if (which == 0) {
        float* o = g_xq + (long)prow*kC + f0;
        #pragma unroll
        for (int q = 0; q < 8; q++)
            reinterpret_cast<float4*>(o)[q] =
                make_float4(acc[q*4+0], acc[q*4+1], acc[q*4+2], acc[q*4+3]);
        #pragma unroll
        for (int q = 0; q < 4; q++) {
            reinterpret_cast<uint4*>(g_xq_h)[u4base+q] = make_uint4(hw_[4*q],hw_[4*q+1],hw_[4*q+2],hw_[4*q+3]);
            reinterpret_cast<uint4*>(g_xq_l)[u4base+q] = make_uint4(lw_[4*q],lw_[4*q+1],lw_[4*q+2],lw_[4*q+3]);
        }
    } else {
        #pragma unroll
        for (int q = 0; q < 4; q++) {
            reinterpret_cast<uint4*>(g_yk_h)[u4base+q] = make_uint4(hw_[4*q],hw_[4*q+1],hw_[4*q+2],hw_[4*q+3]);
            reinterpret_cast<uint4*>(g_yk_l)[u4base+q] = make_uint4(lw_[4*q],lw_[4*q+1],lw_[4*q+2],lw_[4*q+3]);
        }
        const int bb = prow >> 12, pb = prow & 4095;
        #pragma unroll
        for (int i = 0; i < 32; i++) {            // coalesced: lanes = consecutive pb
            int idx = (bb*kC + f0 + i)*kHW + pb;
            g_yt_h[idx] = hs[i];
            g_yt_l[idx] = ls[i];
        }
    }
}

// ---------------------------------------------------------------------------
// j-tile loader: XQ hi/lo [32 x 128] + YT hi/lo [128 x 32] via cp.async
// 128 threads.
// ---------------------------------------------------------------------------
__device__ __forceinline__ void load_jtile(uint32_t su, int buf, long pix0,
                                           int bIdx, int j0, int tid) {
    const uint32_t base = su + buf * BUF_BYTES;
    #pragma unroll
    for (int k = 0; k < 4; k++) {                 // XQ: 512 chunks each
        int idx = tid + k*128, row = idx >> 4, q = idx & 15;
        CP16(base + XQH_OFF + row*272 + q*16, g_xq_h + (pix0 + j0 + row)*kC + q*8);
        CP16(base + XQL_OFF + row*272 + q*16, g_xq_l + (pix0 + j0 + row)*kC + q*8);
    }
    const long ytb = (long)bIdx * kC * kHW + j0;
    #pragma unroll
    for (int k = 0; k < 4; k++) {                 // YT: 512 chunks each
        int idx = tid + k*128, row = idx >> 2, q = idx & 3;
        CP16(base + YTH_OFF + row*80 + q*16, g_yt_h + ytb + (long)row*kHW + q*8);
        CP16(base + YTL_OFF + row*80 + q*16, g_yt_l + ytb + (long)row*kHW + q*8);
    }
}

// ---------------------------------------------------------------------------
// Attention: grid (64 i-tiles, 4 batches) = 256 CTAs, block 128 (4 warps),
// 2 CTAs resident per SM (93KB smem each).
// ---------------------------------------------------------------------------
__global__ __launch_bounds__(128, 2) void attn_mma(float* __restrict__ out)
{
    extern __shared__ char smem[];
    const uint32_t su = smem_u32(smem);
    uint32_t* s32 = reinterpret_cast<uint32_t*>(smem);
    const int tid = threadIdx.x, w = tid >> 5, lane = tid & 31;
    const int r0 = lane >> 2, qd = lane & 3;
    const int b = blockIdx.y, i0 = blockIdx.x * TI;
    const long pix0 = (long)b * kHW;

    // prologue: j-tile 0 + resident YKi_lo via cp.async
    load_jtile(su, 0, pix0, b, 0, tid);
    #pragma unroll
    for (int k = 0; k < 8; k++) {                 // YKi_lo: 1024 chunks
        int idx = tid + k*128, row = idx >> 4, q = idx & 15;
        CP16(su + YKIL_OFF + row*272 + q*16, g_yk_l + (pix0 + i0 + row)*kC + q*8);
    }
    CP_COMMIT();

    // YKi_hi A-fragments straight from gmem (one-time)
    uint32_t aH[8][4];
    const unsigned short* ykb = g_yk_h + (pix0 + i0 + w*16) * kC;
    #pragma unroll
    for (int kb = 0; kb < 8; kb++) {
        int c0 = kb*16 + 2*qd;
        aH[kb][0] = *reinterpret_cast<const uint32_t*>(ykb +  r0      *kC + c0);
        aH[kb][1] = *reinterpret_cast<const uint32_t*>(ykb + (r0 + 8) *kC + c0);
        aH[kb][2] = *reinterpret_cast<const uint32_t*>(ykb +  r0      *kC + c0 + 8);
        aH[kb][3] = *reinterpret_cast<const uint32_t*>(ykb + (r0 + 8) *kC + c0 + 8);
    }

    float O[16][4];
    #pragma unroll
    for (int nt = 0; nt < 16; nt++)
        #pragma unroll
        for (int e = 0; e < 4; e++) O[nt][e] = 0.f;

    const uint32_t ykl = (uint32_t)(YKIL_OFF >> 2) + (w*16) * XQ_STR;

    for (int j = 0; j < NJ; j++) {
        const int buf = j & 1;
        CP_WAIT0();
        __syncthreads();
        if (j + 1 < NJ) {
            load_jtile(su, buf ^ 1, pix0, b, (j + 1) * TJ, tid);
            CP_COMMIT();
        }

        const uint32_t bb  = (uint32_t)(buf * BUF_BYTES) >> 2;
        const uint32_t xqh = bb + (XQH_OFF >> 2), xql = bb + (XQL_OFF >> 2);

        // ---- S = YKi @ XQj^T (hh + hl + lh), 16 rows x 32 j per warp ----
        float S[4][4];
        #pragma unroll
        for (int nt = 0; nt < 4; nt++)
            #pragma unroll
            for (int e = 0; e < 4; e++) S[nt][e] = 0.f;

        #pragma unroll
        for (int kb = 0; kb < 8; kb++) {
            uint32_t aL[4];
            const uint32_t ai = ykl + r0*XQ_STR + kb*8 + qd;
            aL[0] = s32[ai];
            aL[1] = s32[ai + 8*XQ_STR];
            aL[2] = s32[ai + 4];
            aL[3] = s32[ai + 8*XQ_STR + 4];
            #pragma unroll
            for (int nt = 0; nt < 4; nt++) {
                const uint32_t bi = (uint32_t)(8*nt + r0)*XQ_STR + kb*8 + qd;
                uint32_t bh0 = s32[xqh + bi], bh1 = s32[xqh + bi + 4];
                uint32_t bl0 = s32[xql + bi], bl1 = s32[xql + bi + 4];
                mma_bf16(S[nt], aH[kb], bh0, bh1);
                mma_bf16(S[nt], aH[kb], bl0, bl1);
                mma_bf16(S[nt], aL,     bh0, bh1);
            }
        }

        // ---- sigmoid (exact: EX2 + RCP) ----
        #pragma unroll
        for (int nt = 0; nt < 4; nt++)
            #pragma unroll
            for (int e = 0; e < 4; e++) {
                float ev = __expf(-S[nt][e]);
                S[nt][e] = __fdividef(1.f, 1.f + ev);
            }

        // ---- pack A-fragments: accumulator layout == A-operand layout ----
        uint32_t aPh[2][4], aPl[2][4];
        #pragma unroll
        for (int kb = 0; kb < 2; kb++) {
            packHL(S[2*kb  ][0], S[2*kb  ][1], aPh[kb][0], aPl[kb][0]);
            packHL(S[2*kb  ][2], S[2*kb  ][3], aPh[kb][1], aPl[kb][1]);
            packHL(S[2*kb+1][0], S[2*kb+1][1], aPh[kb][2], aPl[kb][2]);
            packHL(S[2*kb+1][2], S[2*kb+1][3], aPh[kb][3], aPl[kb][3]);
        }

        // ---- O += A @ YKj (hh + hl + lh), B from transposed-YK tile ----
        const uint32_t yth = bb + (YTH_OFF >> 2), ytl = bb + (YTL_OFF >> 2);
        #pragma unroll
        for (int nt = 0; nt < 16; nt++) {
            #pragma unroll
            for (int kb = 0; kb < 2; kb++) {
                const uint32_t bi = (uint32_t)(8*nt + r0)*YT_STR + kb*8 + qd;
                uint32_t bh0 = s32[yth + bi], bh1 = s32[yth + bi + 4];
                uint32_t bl0 = s32[ytl + bi], bl1 = s32[ytl + bi + 4];
                mma_bf16(O[nt], aPh[kb], bh0, bh1);
                mma_bf16(O[nt], aPh[kb], bl0, bl1);
                mma_bf16(O[nt], aPl[kb], bh0, bh1);
            }
        }
    }

    // ---- epilogue: out = O + XQ (fp32 residual) ----
    const long rowbase = pix0 + i0 + w*16;
    #pragma unroll
    for (int nt = 0; nt < 16; nt++) {
        const int c = 8*nt + 2*qd;
        const long o0 = (rowbase + r0    ) * kC + c;
        const long o1 = (rowbase + r0 + 8) * kC + c;
        float2 q0 = *reinterpret_cast<const float2*>(g_xq + o0);
        float2 q1 = *reinterpret_cast<const float2*>(g_xq + o1);
        *reinterpret_cast<float2*>(out + o0) = make_float2(O[nt][0] + q0.x, O[nt][1] + q0.y);
        *reinterpret_cast<float2*>(out + o1) = make_float2(O[nt][2] + q1.x, O[nt][3] + q1.y);
    }
}

// ---------------------------------------------------------------------------
extern "C" void kernel_launch(void* const* d_in, const int* in_sizes, int n_in,
                              void* d_out, int out_size)
{
    const float* x  = (const float*)d_in[0];
    const float* y  = (const float*)d_in[1];
    const float* W1 = (const float*)d_in[2];
    const float* b1 = (const float*)d_in[3];
    const float* W2 = (const float*)d_in[4];
    const float* b2 = (const float*)d_in[5];

    cudaFuncSetAttribute(attn_mma, cudaFuncAttributeMaxDynamicSharedMemorySize, SMEM_TOTAL);

    proj_kernel<<<dim3(256, 2), 256>>>(x, y, W1, b1, W2, b2);
    attn_mma<<<dim3(64, 4), 128, SMEM_TOTAL>>>((float*)d_out);
}

// round 9
// speedup vs baseline: 1.0629x; 1.0629x over previous
#include <cuda_runtime.h>
#include <cuda_bf16.h>
#include <cstdint>

// ============================================================================
// out = sigmoid(YK @ XQ^T) @ YK + XQ ;  XQ = x@W1+b1, YK = y@W2+b2
// B=4, HW=4096, C=NF=128 fp32.
// mma.sync bf16 hi/lo split (hh+hl+lh). R9 = R8 resubmit (round 8 bench was an
// infra-side container failure; kernel audit clean): R6 tiles (TI=128, TJ=64),
// 512 threads / 16 warps, j-dim split across two warp groups (4 warps/SMSP) so
// sigmoid/LDS phases of one warp overlap HMMAs of another. Partial-O smem
// reduction at the end.
// ============================================================================

constexpr int kB = 4, kHW = 4096, kC = 128;
constexpr int TJ = 64, NJ = kHW / TJ;     // 64-wide j tiles
constexpr int TI = 128;

// smem strides in b32 units (stride ≡ 4 mod 32 -> conflict-free frag access)
constexpr int XQ_STR = 68;   // 128 bf16 + 8 pad  (272 B/row)
constexpr int YT_STR = 36;   // 64 bf16 + 8 pad   (144 B/row)

// smem byte layout: two j-tile buffers + resident YKi hi/lo
constexpr int XQH_OFF = 0;                      // 64 x 272 = 17408 B
constexpr int XQL_OFF = 17408;
constexpr int YTH_OFF = 34816;                  // 128 x 144 = 18432 B
constexpr int YTL_OFF = 53248;
constexpr int BUF_BYTES = 71680;
constexpr int YKIH_OFF = 2 * BUF_BYTES;         // 128 x 272 = 34816 B
constexpr int YKIL_OFF = YKIH_OFF + 34816;
constexpr int SMEM_TOTAL = YKIL_OFF + 34816;    // 212992 B (1 CTA/SM)
constexpr int SROW = 132;                       // epilogue staging stride (b32)

// global scratch (allocation-free rule)
__device__ float          g_xq  [kB*kHW*kC];
__device__ unsigned short g_xq_h[kB*kHW*kC], g_xq_l[kB*kHW*kC];
__device__ unsigned short g_yk_h[kB*kHW*kC], g_yk_l[kB*kHW*kC];
__device__ unsigned short g_yt_h[kB*kHW*kC], g_yt_l[kB*kHW*kC];  // [b][feat][pix]

// ---------------------------------------------------------------------------
__device__ __forceinline__ uint32_t smem_u32(const void* p) {
    uint32_t a;
    asm("{ .reg .u64 t; cvta.to.shared.u64 t, %1; cvt.u32.u64 %0, t; }" : "=r"(a) : "l"(p));
    return a;
}
#define CP16(sm_addr, g_ptr) \
    asm volatile("cp.async.cg.shared.global [%0], [%1], 16;" \
        :: "r"(sm_addr), "l"(__cvta_generic_to_global(g_ptr)) : "memory")
#define CP_COMMIT() asm volatile("cp.async.commit_group;" ::: "memory")
#define CP_WAIT0()  asm volatile("cp.async.wait_group 0;" ::: "memory")

__device__ __forceinline__ void mma_bf16(float* d, const uint32_t* a,
                                         uint32_t b0, uint32_t b1) {
    asm volatile(
        "mma.sync.aligned.m16n8k16.row.col.f32.bf16.bf16.f32 "
        "{%0,%1,%2,%3}, {%4,%5,%6,%7}, {%8,%9}, {%0,%1,%2,%3};"
        : "+f"(d[0]), "+f"(d[1]), "+f"(d[2]), "+f"(d[3])
        : "r"(a[0]), "r"(a[1]), "r"(a[2]), "r"(a[3]), "r"(b0), "r"(b1));
}
__device__ __forceinline__ void packHL(float a0, float a1, uint32_t& hi, uint32_t& lo) {
    __nv_bfloat16 h0 = __float2bfloat16(a0), h1 = __float2bfloat16(a1);
    float l0 = a0 - __bfloat162float(h0);
    float l1 = a1 - __bfloat162float(h1);
    hi = (uint32_t)__bfloat16_as_ushort(h0) | ((uint32_t)__bfloat16_as_ushort(h1) << 16);
    asm("cvt.rn.bf16x2.f32 %0, %1, %2;" : "=r"(lo) : "f"(l1), "f"(l0));
}

// ---------------------------------------------------------------------------
// Projection (unchanged): XQ/YK fp32 + bf16 hi/lo splits + YK^T copy.
// ---------------------------------------------------------------------------
__global__ __launch_bounds__(256) void proj_kernel(
    const float* __restrict__ x,  const float* __restrict__ y,
    const float* __restrict__ W1, const float* __restrict__ b1,
    const float* __restrict__ W2, const float* __restrict__ b2)
{
    __shared__ float  xs[64][129];
    __shared__ float4 ws[16][32];

    const int which = blockIdx.y;
    const float* in   = which ? y  : x;
    const float* W    = which ? W2 : W1;
    const float* bias = which ? b2 : b1;

    const int base = blockIdx.x * 64;
    const int t = threadIdx.x, row = t & 63, fgrp = t >> 6, f0 = fgrp * 32;

    for (int v = t; v < 64*32; v += 256) {
        int r = v >> 5, c4 = v & 31;
        float4 d = reinterpret_cast<const float4*>(in + (long)(base + r)*kC)[c4];
        xs[r][c4*4+0]=d.x; xs[r][c4*4+1]=d.y; xs[r][c4*4+2]=d.z; xs[r][c4*4+3]=d.w;
    }
    float acc[32];
    #pragma unroll
    for (int i = 0; i < 32; i++) acc[i] = bias[f0 + i];

    for (int c0 = 0; c0 < kC; c0 += 16) {
        __syncthreads();
        for (int v = t; v < 16*32; v += 256) {
            int r = v >> 5, c4 = v & 31;
            ws[r][c4] = reinterpret_cast<const float4*>(W + (long)(c0 + r)*kC)[c4];
        }
        __syncthreads();
        #pragma unroll
        for (int cc = 0; cc < 16; cc++) {
            float xv = xs[row][c0 + cc];
            #pragma unroll
            for (int q = 0; q < 8; q++) {
                float4 w = ws[cc][fgrp*8 + q];
                acc[q*4+0] += xv*w.x; acc[q*4+1] += xv*w.y;
                acc[q*4+2] += xv*w.z; acc[q*4+3] += xv*w.w;
            }
        }
    }

    const int prow = base + row;
    unsigned short hs[32], ls[32];
    #pragma unroll
    for (int i = 0; i < 32; i++) {
        float v = acc[i];
        __nv_bfloat16 h = __float2bfloat16(v);
        float lf = v - __bfloat162float(h);
        hs[i] = __bfloat16_as_ushort(h);
        ls[i] = __bfloat16_as_ushort(__float2bfloat16(lf));
    }
    unsigned hw_[16], lw_[16];
    #pragma unroll
    for (int k = 0; k < 16; k++) {
        hw_[k] = (unsigned)hs[2*k] | ((unsigned)hs[2*k+1] << 16);
        lw_[k] = (unsigned)ls[2*k] | ((unsigned)ls[2*k+1] << 16);
    }
    const int u4base = prow * 16 + fgrp * 4;

    if (which == 0) {
        float* o = g_xq + (long)prow*kC + f0;
        #pragma unroll
        for (int q = 0; q < 8; q++)
            reinterpret_cast<float4*>(o)[q] =
                make_float4(acc[q*4+0], acc[q*4+1], acc[q*4+2], acc[q*4+3]);
        #pragma unroll
        for (int q = 0; q < 4; q++) {
            reinterpret_cast<uint4*>(g_xq_h)[u4base+q] = make_uint4(hw_[4*q],hw_[4*q+1],hw_[4*q+2],hw_[4*q+3]);
            reinterpret_cast<uint4*>(g_xq_l)[u4base+q] = make_uint4(lw_[4*q],lw_[4*q+1],lw_[4*q+2],lw_[4*q+3]);
        }
    } else {
        #pragma unroll
        for (int q = 0; q < 4; q++) {
            reinterpret_cast<uint4*>(g_yk_h)[u4base+q] = make_uint4(hw_[4*q],hw_[4*q+1],hw_[4*q+2],hw_[4*q+3]);
            reinterpret_cast<uint4*>(g_yk_l)[u4base+q] = make_uint4(lw_[4*q],lw_[4*q+1],lw_[4*q+2],lw_[4*q+3]);
        }
        const int bb = prow >> 12, pb = prow & 4095;
        #pragma unroll
        for (int i = 0; i < 32; i++) {
            int idx = (bb*kC + f0 + i)*kHW + pb;
            g_yt_h[idx] = hs[i];
            g_yt_l[idx] = ls[i];
        }
    }
}

// ---------------------------------------------------------------------------
// j-tile loader: XQ hi/lo [64 x 128] + YT hi/lo [128 x 64], 512 threads.
// ---------------------------------------------------------------------------
__device__ __forceinline__ void load_jtile(uint32_t su, int buf, long pix0,
                                           int bIdx, int j0, int tid) {
    const uint32_t base = su + buf * BUF_BYTES;
    #pragma unroll
    for (int k = 0; k < 2; k++) {                 // XQ: 1024 chunks each
        int idx = tid + k*512, row = idx >> 4, q = idx & 15;
        CP16(base + XQH_OFF + row*272 + q*16, g_xq_h + (pix0 + j0 + row)*kC + q*8);
        CP16(base + XQL_OFF + row*272 + q*16, g_xq_l + (pix0 + j0 + row)*kC + q*8);
    }
    const long ytb = (long)bIdx * kC * kHW + j0;
    #pragma unroll
    for (int k = 0; k < 2; k++) {                 // YT: 1024 chunks each
        int idx = tid + k*512, row = idx >> 3, q = idx & 7;
        CP16(base + YTH_OFF + row*144 + q*16, g_yt_h + ytb + (long)row*kHW + q*8);
        CP16(base + YTL_OFF + row*144 + q*16, g_yt_l + ytb + (long)row*kHW + q*8);
    }
}

// ---------------------------------------------------------------------------
// Attention: grid (32 i-tiles, 4 batches) = 128 CTAs, block 512 (16 warps).
// Warp w: i-rows (w&7)*16..+16, j-half (w>>3)*32. Partial O reduced via smem.
// ---------------------------------------------------------------------------
__global__ __launch_bounds__(512) void attn_mma(float* __restrict__ out)
{
    extern __shared__ char smem[];
    const uint32_t su = smem_u32(smem);
    uint32_t* s32 = reinterpret_cast<uint32_t*>(smem);
    const int tid = threadIdx.x, w = tid >> 5, lane = tid & 31;
    const int r0 = lane >> 2, qd = lane & 3;
    const int jg = w >> 3, wi = w & 7;
    const int b = blockIdx.y, i0 = blockIdx.x * TI;
    const long pix0 = (long)b * kHW;

    // prologue: j-tile 0 + resident YKi hi/lo via cp.async
    load_jtile(su, 0, pix0, b, 0, tid);
    #pragma unroll
    for (int k = 0; k < 4; k++) {                 // YKi h+l: 2048 chunks each
        int idx = tid + k*512, row = idx >> 4, q = idx & 15;
        CP16(su + YKIH_OFF + row*272 + q*16, g_yk_h + (pix0 + i0 + row)*kC + q*8);
        CP16(su + YKIL_OFF + row*272 + q*16, g_yk_l + (pix0 + i0 + row)*kC + q*8);
    }
    CP_COMMIT();

    float O[16][4];
    #pragma unroll
    for (int nt = 0; nt < 16; nt++)
        #pragma unroll
        for (int e = 0; e < 4; e++) O[nt][e] = 0.f;

    const uint32_t ykh = (uint32_t)(YKIH_OFF >> 2) + (wi*16 + r0) * XQ_STR + qd;
    const uint32_t ykl = (uint32_t)(YKIL_OFF >> 2) + (wi*16 + r0) * XQ_STR + qd;

    for (int j = 0; j < NJ; j++) {
        const int buf = j & 1;
        CP_WAIT0();
        __syncthreads();
        if (j + 1 < NJ) {
            load_jtile(su, buf ^ 1, pix0, b, (j + 1) * TJ, tid);
            CP_COMMIT();
        }

        const uint32_t bb  = (uint32_t)(buf * BUF_BYTES) >> 2;
        const uint32_t xqh = bb + (XQH_OFF >> 2), xql = bb + (XQL_OFF >> 2);

        // ---- S = YKi @ XQj^T (hh + hl + lh), 16 rows x 32 j (this warp) ----
        float S[4][4];
        #pragma unroll
        for (int nt = 0; nt < 4; nt++)
            #pragma unroll
            for (int e = 0; e < 4; e++) S[nt][e] = 0.f;

        #pragma unroll
        for (int kb = 0; kb < 8; kb++) {
            uint32_t aH[4], aL[4];
            const uint32_t ah = ykh + kb*8, al = ykl + kb*8;
            aH[0] = s32[ah];               aL[0] = s32[al];
            aH[1] = s32[ah + 8*XQ_STR];    aL[1] = s32[al + 8*XQ_STR];
            aH[2] = s32[ah + 4];           aL[2] = s32[al + 4];
            aH[3] = s32[ah + 8*XQ_STR+4];  aL[3] = s32[al + 8*XQ_STR+4];
            #pragma unroll
            for (int nt = 0; nt < 4; nt++) {
                const uint32_t bi = (uint32_t)(jg*32 + 8*nt + r0)*XQ_STR + kb*8 + qd;
                uint32_t bh0 = s32[xqh + bi], bh1 = s32[xqh + bi + 4];
                uint32_t bl0 = s32[xql + bi], bl1 = s32[xql + bi + 4];
                mma_bf16(S[nt], aH, bh0, bh1);
                mma_bf16(S[nt], aH, bl0, bl1);
                mma_bf16(S[nt], aL, bh0, bh1);
            }
        }

        // ---- sigmoid (exact: EX2 + RCP) ----
        #pragma unroll
        for (int nt = 0; nt < 4; nt++)
            #pragma unroll
            for (int e = 0; e < 4; e++) {
                float ev = __expf(-S[nt][e]);
                S[nt][e] = __fdividef(1.f, 1.f + ev);
            }

        // ---- pack A-fragments (accumulator layout == A-operand layout) ----
        uint32_t aPh[2][4], aPl[2][4];
        #pragma unroll
        for (int kb = 0; kb < 2; kb++) {
            packHL(S[2*kb  ][0], S[2*kb  ][1], aPh[kb][0], aPl[kb][0]);
            packHL(S[2*kb  ][2], S[2*kb  ][3], aPh[kb][1], aPl[kb][1]);
            packHL(S[2*kb+1][0], S[2*kb+1][1], aPh[kb][2], aPl[kb][2]);
            packHL(S[2*kb+1][2], S[2*kb+1][3], aPh[kb][3], aPl[kb][3]);
        }

        // ---- O += A @ YKj over this warp's k-half ----
        const uint32_t yth = bb + (YTH_OFF >> 2), ytl = bb + (YTL_OFF >> 2);
        #pragma unroll
        for (int nt = 0; nt < 16; nt++) {
            #pragma unroll
            for (int kb = 0; kb < 2; kb++) {
                const uint32_t bi = (uint32_t)(8*nt + r0)*YT_STR + (jg*2 + kb)*8 + qd;
                uint32_t bh0 = s32[yth + bi], bh1 = s32[yth + bi + 4];
                uint32_t bl0 = s32[ytl + bi], bl1 = s32[ytl + bi + 4];
                mma_bf16(O[nt], aPh[kb], bh0, bh1);
                mma_bf16(O[nt], aPh[kb], bl0, bl1);
                mma_bf16(O[nt], aPl[kb], bh0, bh1);
            }
        }
    }

    // ---- partial-O reduction (jg0 stages in smem; jg1 adds + residual) ----
    __syncthreads();                       // everyone done with buffer reads
    float* stg = reinterpret_cast<float*>(smem);   // 128 x SROW floats (buf0)
    if (jg == 0) {
        #pragma unroll
        for (int nt = 0; nt < 16; nt++) {
            const int c = 8*nt + 2*qd;
            *reinterpret_cast<float2*>(&stg[(wi*16 + r0    )*SROW + c]) =
                make_float2(O[nt][0], O[nt][1]);
            *reinterpret_cast<float2*>(&stg[(wi*16 + r0 + 8)*SROW + c]) =
                make_float2(O[nt][2], O[nt][3]);
        }
    }
    __syncthreads();
    if (jg == 1) {
        const long rowbase = pix0 + i0 + wi*16;
        #pragma unroll
        for (int nt = 0; nt < 16; nt++) {
            const int c = 8*nt + 2*qd;
            const long o0 = (rowbase + r0    ) * kC + c;
            const long o1 = (rowbase + r0 + 8) * kC + c;
            float2 p0 = *reinterpret_cast<const float2*>(&stg[(wi*16 + r0    )*SROW + c]);
            float2 p1 = *reinterpret_cast<const float2*>(&stg[(wi*16 + r0 + 8)*SROW + c]);
            float2 q0 = *reinterpret_cast<const float2*>(g_xq + o0);
            float2 q1 = *reinterpret_cast<const float2*>(g_xq + o1);
            *reinterpret_cast<float2*>(out + o0) =
                make_float2(O[nt][0] + p0.x + q0.x, O[nt][1] + p0.y + q0.y);
            *reinterpret_cast<float2*>(out + o1) =
                make_float2(O[nt][2] + p1.x + q1.x, O[nt][3] + p1.y + q1.y);
        }
    }
}

// ---------------------------------------------------------------------------
extern "C" void kernel_launch(void* const* d_in, const int* in_sizes, int n_in,
                              void* d_out, int out_size)
{
    const float* x  = (const float*)d_in[0];
    const float* y  = (const float*)d_in[1];
    const float* W1 = (const float*)d_in[2];
    const float* b1 = (const float*)d_in[3];
    const float* W2 = (const float*)d_in[4];
    const float* b2 = (const float*)d_in[5];

    cudaFuncSetAttribute(attn_mma, cudaFuncAttributeMaxDynamicSharedMemorySize, SMEM_TOTAL);

    proj_kernel<<<dim3(256, 2), 256>>>(x, y, W1, b1, W2, b2);
    attn_mma<<<dim3(32, 4), 512, SMEM_TOTAL>>>((float*)d_out);
}

// round 10
// speedup vs baseline: 1.1193x; 1.0531x over previous
#include <cuda_runtime.h>
#include <cuda_bf16.h>
#include <cstdint>

// ============================================================================
// out = sigmoid(YK @ XQ^T) @ YK + XQ ;  XQ = x@W1+b1, YK = y@W2+b2
// B=4, HW=4096, C=NF=128 fp32.
// mma.sync bf16 hi/lo split (hh+hl+lh). R10 = R6 base (TI=128, TJ=64, 8 warps)
// + rolling 1-step B-fragment prefetch in both MMA loops (cover LDS latency
// inside each warp) + aH AND aL resident in registers (no YKi smem stage).
// ============================================================================

constexpr int kB = 4, kHW = 4096, kC = 128;
constexpr int TJ = 64, NJ = kHW / TJ;     // 64-wide j tiles
constexpr int TI = 128;

// smem strides in b32 units (bank = 4*(lane/4)+(lane%4) -> conflict-free)
constexpr int XQ_STR = 68;   // 128 bf16 + 8 pad  (272 B/row)
constexpr int YT_STR = 36;   // 64 bf16 + 8 pad   (144 B/row)

// smem: two j-tile buffers only (YKi now lives in registers)
constexpr int XQH_OFF = 0;                      // 64 x 272 = 17408 B
constexpr int XQL_OFF = 17408;
constexpr int YTH_OFF = 34816;                  // 128 x 144 = 18432 B
constexpr int YTL_OFF = 53248;
constexpr int BUF_BYTES = 71680;
constexpr int SMEM_TOTAL = 2 * BUF_BYTES;       // 143360 B

// global scratch (allocation-free rule)
__device__ float          g_xq  [kB*kHW*kC];
__device__ unsigned short g_xq_h[kB*kHW*kC], g_xq_l[kB*kHW*kC];
__device__ unsigned short g_yk_h[kB*kHW*kC], g_yk_l[kB*kHW*kC];
__device__ unsigned short g_yt_h[kB*kHW*kC], g_yt_l[kB*kHW*kC];  // [b][feat][pix]

// ---------------------------------------------------------------------------
__device__ __forceinline__ uint32_t smem_u32(const void* p) {
    uint32_t a;
    asm("{ .reg .u64 t; cvta.to.shared.u64 t, %1; cvt.u32.u64 %0, t; }" : "=r"(a) : "l"(p));
    return a;
}
#define CP16(sm_addr, g_ptr) \
    asm volatile("cp.async.cg.shared.global [%0], [%1], 16;" \
        :: "r"(sm_addr), "l"(__cvta_generic_to_global(g_ptr)) : "memory")
#define CP_COMMIT() asm volatile("cp.async.commit_group;" ::: "memory")
#define CP_WAIT0()  asm volatile("cp.async.wait_group 0;" ::: "memory")

__device__ __forceinline__ void mma_bf16(float* d, const uint32_t* a,
                                         uint32_t b0, uint32_t b1) {
    asm volatile(
        "mma.sync.aligned.m16n8k16.row.col.f32.bf16.bf16.f32 "
        "{%0,%1,%2,%3}, {%4,%5,%6,%7}, {%8,%9}, {%0,%1,%2,%3};"
        : "+f"(d[0]), "+f"(d[1]), "+f"(d[2]), "+f"(d[3])
        : "r"(a[0]), "r"(a[1]), "r"(a[2]), "r"(a[3]), "r"(b0), "r"(b1));
}
__device__ __forceinline__ void packHL(float a0, float a1, uint32_t& hi, uint32_t& lo) {
    __nv_bfloat16 h0 = __float2bfloat16(a0), h1 = __float2bfloat16(a1);
    float l0 = a0 - __bfloat162float(h0);
    float l1 = a1 - __bfloat162float(h1);
    hi = (uint32_t)__bfloat16_as_ushort(h0) | ((uint32_t)__bfloat16_as_ushort(h1) << 16);
    asm("cvt.rn.bf16x2.f32 %0, %1, %2;" : "=r"(lo) : "f"(l1), "f"(l0));
}

// ---------------------------------------------------------------------------
// Projection (unchanged): XQ/YK fp32 + bf16 hi/lo splits + YK^T copy.
// ---------------------------------------------------------------------------
__global__ __launch_bounds__(256) void proj_kernel(
    const float* __restrict__ x,  const float* __restrict__ y,
    const float* __restrict__ W1, const float* __restrict__ b1,
    const float* __restrict__ W2, const float* __restrict__ b2)
{
    __shared__ float  xs[64][129];
    __shared__ float4 ws[16][32];

    const int which = blockIdx.y;
    const float* in   = which ? y  : x;
    const float* W    = which ? W2 : W1;
    const float* bias = which ? b2 : b1;

    const int base = blockIdx.x * 64;
    const int t = threadIdx.x, row = t & 63, fgrp = t >> 6, f0 = fgrp * 32;

    for (int v = t; v < 64*32; v += 256) {
        int r = v >> 5, c4 = v & 31;
        float4 d = reinterpret_cast<const float4*>(in + (long)(base + r)*kC)[c4];
        xs[r][c4*4+0]=d.x; xs[r][c4*4+1]=d.y; xs[r][c4*4+2]=d.z; xs[r][c4*4+3]=d.w;
    }
    float acc[32];
    #pragma unroll
    for (int i = 0; i < 32; i++) acc[i] = bias[f0 + i];

    for (int c0 = 0; c0 < kC; c0 += 16) {
        __syncthreads();
        for (int v = t; v < 16*32; v += 256) {
            int r = v >> 5, c4 = v & 31;
            ws[r][c4] = reinterpret_cast<const float4*>(W + (long)(c0 + r)*kC)[c4];
        }
        __syncthreads();
        #pragma unroll
        for (int cc = 0; cc < 16; cc++) {
            float xv = xs[row][c0 + cc];
            #pragma unroll
            for (int q = 0; q < 8; q++) {
                float4 w = ws[cc][fgrp*8 + q];
                acc[q*4+0] += xv*w.x; acc[q*4+1] += xv*w.y;
                acc[q*4+2] += xv*w.z; acc[q*4+3] += xv*w.w;
            }
        }
    }

    const int prow = base + row;
    unsigned short hs[32], ls[32];
    #pragma unroll
    for (int i = 0; i < 32; i++) {
        float v = acc[i];
        __nv_bfloat16 h = __float2bfloat16(v);
        float lf = v - __bfloat162float(h);
        hs[i] = __bfloat16_as_ushort(h);
        ls[i] = __bfloat16_as_ushort(__float2bfloat16(lf));
    }
    unsigned hw_[16], lw_[16];
    #pragma unroll
    for (int k = 0; k < 16; k++) {
        hw_[k] = (unsigned)hs[2*k] | ((unsigned)hs[2*k+1] << 16);
        lw_[k] = (unsigned)ls[2*k] | ((unsigned)ls[2*k+1] << 16);
    }
    const int u4base = prow * 16 + fgrp * 4;

    if (which == 0) {
        float* o = g_xq + (long)prow*kC + f0;
        #pragma unroll
        for (int q = 0; q < 8; q++)
            reinterpret_cast<float4*>(o)[q] =
                make_float4(acc[q*4+0], acc[q*4+1], acc[q*4+2], acc[q*4+3]);
        #pragma unroll
        for (int q = 0; q < 4; q++) {
            reinterpret_cast<uint4*>(g_xq_h)[u4base+q] = make_uint4(hw_[4*q],hw_[4*q+1],hw_[4*q+2],hw_[4*q+3]);
            reinterpret_cast<uint4*>(g_xq_l)[u4base+q] = make_uint4(lw_[4*q],lw_[4*q+1],lw_[4*q+2],lw_[4*q+3]);
        }
    } else {
        #pragma unroll
        for (int q = 0; q < 4; q++) {
            reinterpret_cast<uint4*>(g_yk_h)[u4base+q] = make_uint4(hw_[4*q],hw_[4*q+1],hw_[4*q+2],hw_[4*q+3]);
            reinterpret_cast<uint4*>(g_yk_l)[u4base+q] = make_uint4(lw_[4*q],lw_[4*q+1],lw_[4*q+2],lw_[4*q+3]);
        }
        const int bb = prow >> 12, pb = prow & 4095;
        #pragma unroll
        for (int i = 0; i < 32; i++) {
            int idx = (bb*kC + f0 + i)*kHW + pb;
            g_yt_h[idx] = hs[i];
            g_yt_l[idx] = ls[i];
        }
    }
}

// ---------------------------------------------------------------------------
// j-tile loader: XQ hi/lo [64 x 128] + YT hi/lo [128 x 64] via cp.async (256 thr)
// ---------------------------------------------------------------------------
__device__ __forceinline__ void load_jtile(uint32_t su, int buf, long pix0,
                                           int bIdx, int j0, int tid) {
    const uint32_t base = su + buf * BUF_BYTES;
    #pragma unroll
    for (int k = 0; k < 4; k++) {                 // XQ: 1024 chunks each
        int idx = tid + k*256, row = idx >> 4, q = idx & 15;
        CP16(base + XQH_OFF + row*272 + q*16, g_xq_h + (pix0 + j0 + row)*kC + q*8);
        CP16(base + XQL_OFF + row*272 + q*16, g_xq_l + (pix0 + j0 + row)*kC + q*8);
    }
    const long ytb = (long)bIdx * kC * kHW + j0;
    #pragma unroll
    for (int k = 0; k < 4; k++) {                 // YT: 1024 chunks each
        int idx = tid + k*256, row = idx >> 3, q = idx & 7;
        CP16(base + YTH_OFF + row*144 + q*16, g_yt_h + ytb + (long)row*kHW + q*8);
        CP16(base + YTL_OFF + row*144 + q*16, g_yt_l + ytb + (long)row*kHW + q*8);
    }
}

// ---------------------------------------------------------------------------
// Attention: grid (32 i-tiles, 4 batches), block 256 (8 warps x 16 rows)
// ---------------------------------------------------------------------------
__global__ __launch_bounds__(256) void attn_mma(float* __restrict__ out)
{
    extern __shared__ char smem[];
    const uint32_t su = smem_u32(smem);
    uint32_t* s32 = reinterpret_cast<uint32_t*>(smem);
    const int tid = threadIdx.x, w = tid >> 5, lane = tid & 31;
    const int r0 = lane >> 2, qd = lane & 3;
    const int b = blockIdx.y, i0 = blockIdx.x * TI;
    const long pix0 = (long)b * kHW;

    // prologue: j-tile 0 via cp.async
    load_jtile(su, 0, pix0, b, 0, tid);
    CP_COMMIT();

    // YKi hi AND lo A-fragments resident (one-time gmem loads)
    uint32_t aH[8][4], aL[8][4];
    const unsigned short* ykbh = g_yk_h + (pix0 + i0 + w*16) * kC;
    const unsigned short* ykbl = g_yk_l + (pix0 + i0 + w*16) * kC;
    #pragma unroll
    for (int kb = 0; kb < 8; kb++) {
        int c0 = kb*16 + 2*qd;
        aH[kb][0] = *reinterpret_cast<const uint32_t*>(ykbh +  r0      *kC + c0);
        aH[kb][1] = *reinterpret_cast<const uint32_t*>(ykbh + (r0 + 8) *kC + c0);
        aH[kb][2] = *reinterpret_cast<const uint32_t*>(ykbh +  r0      *kC + c0 + 8);
        aH[kb][3] = *reinterpret_cast<const uint32_t*>(ykbh + (r0 + 8) *kC + c0 + 8);
        aL[kb][0] = *reinterpret_cast<const uint32_t*>(ykbl +  r0      *kC + c0);
        aL[kb][1] = *reinterpret_cast<const uint32_t*>(ykbl + (r0 + 8) *kC + c0);
        aL[kb][2] = *reinterpret_cast<const uint32_t*>(ykbl +  r0      *kC + c0 + 8);
        aL[kb][3] = *reinterpret_cast<const uint32_t*>(ykbl + (r0 + 8) *kC + c0 + 8);
    }

    float O[16][4];
    #pragma unroll
    for (int nt = 0; nt < 16; nt++)
        #pragma unroll
        for (int e = 0; e < 4; e++) O[nt][e] = 0.f;

    for (int j = 0; j < NJ; j++) {
        const int buf = j & 1;
        CP_WAIT0();
        __syncthreads();
        if (j + 1 < NJ) {
            load_jtile(su, buf ^ 1, pix0, b, (j + 1) * TJ, tid);
            CP_COMMIT();
        }

        const uint32_t bb  = (uint32_t)(buf * BUF_BYTES) >> 2;
        const uint32_t xqh = bb + (XQH_OFF >> 2), xql = bb + (XQL_OFF >> 2);

        // ---- S = YKi @ XQj^T (hh + hl + lh), rolling 1-step prefetch ----
        float S[8][4];
        #pragma unroll
        for (int nt = 0; nt < 8; nt++)
            #pragma unroll
            for (int e = 0; e < 4; e++) S[nt][e] = 0.f;

        uint32_t c0, c1, c2, c3;
        {   // first fragment (kb=0, nt=0)
            const uint32_t bi = (uint32_t)r0 * XQ_STR + qd;
            c0 = s32[xqh + bi]; c1 = s32[xqh + bi + 4];
            c2 = s32[xql + bi]; c3 = s32[xql + bi + 4];
        }
        #pragma unroll
        for (int kb = 0; kb < 8; kb++) {
            #pragma unroll
            for (int nt = 0; nt < 8; nt++) {
                uint32_t n0 = 0, n1 = 0, n2 = 0, n3 = 0;
                if (!(kb == 7 && nt == 7)) {
                    const int nkb = (nt == 7) ? kb + 1 : kb;
                    const int nnt = (nt == 7) ? 0 : nt + 1;
                    const uint32_t bi = (uint32_t)(8*nnt + r0)*XQ_STR + nkb*8 + qd;
                    n0 = s32[xqh + bi]; n1 = s32[xqh + bi + 4];
                    n2 = s32[xql + bi]; n3 = s32[xql + bi + 4];
                }
                mma_bf16(S[nt], aH[kb], c0, c1);
                mma_bf16(S[nt], aH[kb], c2, c3);
                mma_bf16(S[nt], aL[kb], c0, c1);
                c0 = n0; c1 = n1; c2 = n2; c3 = n3;
            }
        }

        // ---- sigmoid (exact: EX2 + RCP) ----
        #pragma unroll
        for (int nt = 0; nt < 8; nt++)
            #pragma unroll
            for (int e = 0; e < 4; e++) {
                float ev = __expf(-S[nt][e]);
                S[nt][e] = __fdividef(1.f, 1.f + ev);
            }

        // ---- pack A-fragments (accumulator layout == A-operand layout) ----
        uint32_t aPh[4][4], aPl[4][4];
        #pragma unroll
        for (int kb = 0; kb < 4; kb++) {
            packHL(S[2*kb  ][0], S[2*kb  ][1], aPh[kb][0], aPl[kb][0]);
            packHL(S[2*kb  ][2], S[2*kb  ][3], aPh[kb][1], aPl[kb][1]);
            packHL(S[2*kb+1][0], S[2*kb+1][1], aPh[kb][2], aPl[kb][2]);
            packHL(S[2*kb+1][2], S[2*kb+1][3], aPh[kb][3], aPl[kb][3]);
        }

        // ---- O += A @ YKj (hh + hl + lh), rolling 1-step prefetch ----
        const uint32_t yth = bb + (YTH_OFF >> 2), ytl = bb + (YTL_OFF >> 2);
        {
            const uint32_t bi = (uint32_t)r0 * YT_STR + qd;
            c0 = s32[yth + bi]; c1 = s32[yth + bi + 4];
            c2 = s32[ytl + bi]; c3 = s32[ytl + bi + 4];
        }
        #pragma unroll
        for (int nt = 0; nt < 16; nt++) {
            #pragma unroll
            for (int kb = 0; kb < 4; kb++) {
                uint32_t n0 = 0, n1 = 0, n2 = 0, n3 = 0;
                if (!(nt == 15 && kb == 3)) {
                    const int nnt = (kb == 3) ? nt + 1 : nt;
                    const int nkb = (kb == 3) ? 0 : kb + 1;
                    const uint32_t bi = (uint32_t)(8*nnt + r0)*YT_STR + nkb*8 + qd;
                    n0 = s32[yth + bi]; n1 = s32[yth + bi + 4];
                    n2 = s32[ytl + bi]; n3 = s32[ytl + bi + 4];
                }
                mma_bf16(O[nt], aPh[kb], c0, c1);
                mma_bf16(O[nt], aPh[kb], c2, c3);
                mma_bf16(O[nt], aPl[kb], c0, c1);
                c0 = n0; c1 = n1; c2 = n2; c3 = n3;
            }
        }
    }

    // ---- epilogue: out = O + XQ (fp32 residual) ----
    const long rowbase = pix0 + i0 + w*16;
    #pragma unroll
    for (int nt = 0; nt < 16; nt++) {
        const int c = 8*nt + 2*qd;
        const long o0 = (rowbase + r0    ) * kC + c;
        const long o1 = (rowbase + r0 + 8) * kC + c;
        float2 q0 = *reinterpret_cast<const float2*>(g_xq + o0);
        float2 q1 = *reinterpret_cast<const float2*>(g_xq + o1);
        *reinterpret_cast<float2*>(out + o0) = make_float2(O[nt][0] + q0.x, O[nt][1] + q0.y);
        *reinterpret_cast<float2*>(out + o1) = make_float2(O[nt][2] + q1.x, O[nt][3] + q1.y);
    }
}

// ---------------------------------------------------------------------------
extern "C" void kernel_launch(void* const* d_in, const int* in_sizes, int n_in,
                              void* d_out, int out_size)
{
    const float* x  = (const float*)d_in[0];
    const float* y  = (const float*)d_in[1];
    const float* W1 = (const float*)d_in[2];
    const float* b1 = (const float*)d_in[3];
    const float* W2 = (const float*)d_in[4];
    const float* b2 = (const float*)d_in[5];

    cudaFuncSetAttribute(attn_mma, cudaFuncAttributeMaxDynamicSharedMemorySize, SMEM_TOTAL);

    proj_kernel<<<dim3(256, 2), 256>>>(x, y, W1, b1, W2, b2);
    attn_mma<<<dim3(32, 4), 256, SMEM_TOTAL>>>((float*)d_out);
}

// round 11
// speedup vs baseline: 1.1637x; 1.0396x over previous
#include <cuda_runtime.h>
#include <cuda_bf16.h>
#include <cstdint>

// ============================================================================
// out = sigmoid(YK @ XQ^T) @ YK + XQ ;  XQ = x@W1+b1, YK = y@W2+b2
// B=4, HW=4096, C=NF=128 fp32.
// mma.sync bf16 hi/lo split (hh+hl+lh). R11 = R10 + 2-deep double-buffered
// B-fragment prefetch in both MMA loops (load step s+2 after step s's MMAs),
// PV fragments primed before sigmoid, S fragments primed before the cp.async
// burst. Goal: close the ~43% LDS->MMA stall gap (tensor 56.7% -> ~70%).
// ============================================================================

constexpr int kB = 4, kHW = 4096, kC = 128;
constexpr int TJ = 64, NJ = kHW / TJ;     // 64-wide j tiles
constexpr int TI = 128;

// smem strides in b32 units (bank = 4*(lane/4)+(lane%4) -> conflict-free)
constexpr int XQ_STR = 68;   // 128 bf16 + 8 pad  (272 B/row)
constexpr int YT_STR = 36;   // 64 bf16 + 8 pad   (144 B/row)

// smem: two j-tile buffers (YKi lives in registers)
constexpr int XQH_OFF = 0;                      // 64 x 272 = 17408 B
constexpr int XQL_OFF = 17408;
constexpr int YTH_OFF = 34816;                  // 128 x 144 = 18432 B
constexpr int YTL_OFF = 53248;
constexpr int BUF_BYTES = 71680;
constexpr int SMEM_TOTAL = 2 * BUF_BYTES;       // 143360 B

// global scratch (allocation-free rule)
__device__ float          g_xq  [kB*kHW*kC];
__device__ unsigned short g_xq_h[kB*kHW*kC], g_xq_l[kB*kHW*kC];
__device__ unsigned short g_yk_h[kB*kHW*kC], g_yk_l[kB*kHW*kC];
__device__ unsigned short g_yt_h[kB*kHW*kC], g_yt_l[kB*kHW*kC];  // [b][feat][pix]

// ---------------------------------------------------------------------------
__device__ __forceinline__ uint32_t smem_u32(const void* p) {
    uint32_t a;
    asm("{ .reg .u64 t; cvta.to.shared.u64 t, %1; cvt.u32.u64 %0, t; }" : "=r"(a) : "l"(p));
    return a;
}
#define CP16(sm_addr, g_ptr) \
    asm volatile("cp.async.cg.shared.global [%0], [%1], 16;" \
        :: "r"(sm_addr), "l"(__cvta_generic_to_global(g_ptr)) : "memory")
#define CP_COMMIT() asm volatile("cp.async.commit_group;" ::: "memory")
#define CP_WAIT0()  asm volatile("cp.async.wait_group 0;" ::: "memory")

__device__ __forceinline__ void mma_bf16(float* d, const uint32_t* a,
                                         uint32_t b0, uint32_t b1) {
    asm volatile(
        "mma.sync.aligned.m16n8k16.row.col.f32.bf16.bf16.f32 "
        "{%0,%1,%2,%3}, {%4,%5,%6,%7}, {%8,%9}, {%0,%1,%2,%3};"
        : "+f"(d[0]), "+f"(d[1]), "+f"(d[2]), "+f"(d[3])
        : "r"(a[0]), "r"(a[1]), "r"(a[2]), "r"(a[3]), "r"(b0), "r"(b1));
}
__device__ __forceinline__ void packHL(float a0, float a1, uint32_t& hi, uint32_t& lo) {
    __nv_bfloat16 h0 = __float2bfloat16(a0), h1 = __float2bfloat16(a1);
    float l0 = a0 - __bfloat162float(h0);
    float l1 = a1 - __bfloat162float(h1);
    hi = (uint32_t)__bfloat16_as_ushort(h0) | ((uint32_t)__bfloat16_as_ushort(h1) << 16);
    asm("cvt.rn.bf16x2.f32 %0, %1, %2;" : "=r"(lo) : "f"(l1), "f"(l0));
}
// load one step's 4 B-fragments (hi pair + lo pair)
__device__ __forceinline__ void ldfrag(uint32_t* f, const uint32_t* s32,
                                       uint32_t baseh, uint32_t basel, uint32_t bi) {
    f[0] = s32[baseh + bi]; f[1] = s32[baseh + bi + 4];
    f[2] = s32[basel + bi]; f[3] = s32[basel + bi + 4];
}
// hh + hl + lh on one fragment set
__device__ __forceinline__ void mma3(float* d, const uint32_t* aH, const uint32_t* aL,
                                     const uint32_t* f) {
    mma_bf16(d, aH, f[0], f[1]);
    mma_bf16(d, aH, f[2], f[3]);
    mma_bf16(d, aL, f[0], f[1]);
}

// ---------------------------------------------------------------------------
// Projection (unchanged): XQ/YK fp32 + bf16 hi/lo splits + YK^T copy.
// ---------------------------------------------------------------------------
__global__ __launch_bounds__(256) void proj_kernel(
    const float* __restrict__ x,  const float* __restrict__ y,
    const float* __restrict__ W1, const float* __restrict__ b1,
    const float* __restrict__ W2, const float* __restrict__ b2)
{
    __shared__ float  xs[64][129];
    __shared__ float4 ws[16][32];

    const int which = blockIdx.y;
    const float* in   = which ? y  : x;
    const float* W    = which ? W2 : W1;
    const float* bias = which ? b2 : b1;

    const int base = blockIdx.x * 64;
    const int t = threadIdx.x, row = t & 63, fgrp = t >> 6, f0 = fgrp * 32;

    for (int v = t; v < 64*32; v += 256) {
        int r = v >> 5, c4 = v & 31;
        float4 d = reinterpret_cast<const float4*>(in + (long)(base + r)*kC)[c4];
        xs[r][c4*4+0]=d.x; xs[r][c4*4+1]=d.y; xs[r][c4*4+2]=d.z; xs[r][c4*4+3]=d.w;
    }
    float acc[32];
    #pragma unroll
    for (int i = 0; i < 32; i++) acc[i] = bias[f0 + i];

    for (int c0 = 0; c0 < kC; c0 += 16) {
        __syncthreads();
        for (int v = t; v < 16*32; v += 256) {
            int r = v >> 5, c4 = v & 31;
            ws[r][c4] = reinterpret_cast<const float4*>(W + (long)(c0 + r)*kC)[c4];
        }
        __syncthreads();
        #pragma unroll
        for (int cc = 0; cc < 16; cc++) {
            float xv = xs[row][c0 + cc];
            #pragma unroll
            for (int q = 0; q < 8; q++) {
                float4 w = ws[cc][fgrp*8 + q];
                acc[q*4+0] += xv*w.x; acc[q*4+1] += xv*w.y;
                acc[q*4+2] += xv*w.z; acc[q*4+3] += xv*w.w;
            }
        }
    }

    const int prow = base + row;
    unsigned short hs[32], ls[32];
    #pragma unroll
    for (int i = 0; i < 32; i++) {
        float v = acc[i];
        __nv_bfloat16 h = __float2bfloat16(v);
        float lf = v - __bfloat162float(h);
        hs[i] = __bfloat16_as_ushort(h);
        ls[i] = __bfloat16_as_ushort(__float2bfloat16(lf));
    }
    unsigned hw_[16], lw_[16];
    #pragma unroll
    for (int k = 0; k < 16; k++) {
        hw_[k] = (unsigned)hs[2*k] | ((unsigned)hs[2*k+1] << 16);
        lw_[k] = (unsigned)ls[2*k] | ((unsigned)ls[2*k+1] << 16);
    }
    const int u4base = prow * 16 + fgrp * 4;

    if (which == 0) {
        float* o = g_xq + (long)prow*kC + f0;
        #pragma unroll
        for (int q = 0; q < 8; q++)
            reinterpret_cast<float4*>(o)[q] =
                make_float4(acc[q*4+0], acc[q*4+1], acc[q*4+2], acc[q*4+3]);
        #pragma unroll
        for (int q = 0; q < 4; q++) {
            reinterpret_cast<uint4*>(g_xq_h)[u4base+q] = make_uint4(hw_[4*q],hw_[4*q+1],hw_[4*q+2],hw_[4*q+3]);
            reinterpret_cast<uint4*>(g_xq_l)[u4base+q] = make_uint4(lw_[4*q],lw_[4*q+1],lw_[4*q+2],lw_[4*q+3]);
        }
    } else {
        #pragma unroll
        for (int q = 0; q < 4; q++) {
            reinterpret_cast<uint4*>(g_yk_h)[u4base+q] = make_uint4(hw_[4*q],hw_[4*q+1],hw_[4*q+2],hw_[4*q+3]);
            reinterpret_cast<uint4*>(g_yk_l)[u4base+q] = make_uint4(lw_[4*q],lw_[4*q+1],lw_[4*q+2],lw_[4*q+3]);
        }
        const int bb = prow >> 12, pb = prow & 4095;
        #pragma unroll
        for (int i = 0; i < 32; i++) {
            int idx = (bb*kC + f0 + i)*kHW + pb;
            g_yt_h[idx] = hs[i];
            g_yt_l[idx] = ls[i];
        }
    }
}

// ---------------------------------------------------------------------------
// j-tile loader: XQ hi/lo [64 x 128] + YT hi/lo [128 x 64] via cp.async (256 thr)
// ---------------------------------------------------------------------------
__device__ __forceinline__ void load_jtile(uint32_t su, int buf, long pix0,
                                           int bIdx, int j0, int tid) {
    const uint32_t base = su + buf * BUF_BYTES;
    #pragma unroll
    for (int k = 0; k < 4; k++) {                 // XQ: 1024 chunks each
        int idx = tid + k*256, row = idx >> 4, q = idx & 15;
        CP16(base + XQH_OFF + row*272 + q*16, g_xq_h + (pix0 + j0 + row)*kC + q*8);
        CP16(base + XQL_OFF + row*272 + q*16, g_xq_l + (pix0 + j0 + row)*kC + q*8);
    }
    const long ytb = (long)bIdx * kC * kHW + j0;
    #pragma unroll
    for (int k = 0; k < 4; k++) {                 // YT: 1024 chunks each
        int idx = tid + k*256, row = idx >> 3, q = idx & 7;
        CP16(base + YTH_OFF + row*144 + q*16, g_yt_h + ytb + (long)row*kHW + q*8);
        CP16(base + YTL_OFF + row*144 + q*16, g_yt_l + ytb + (long)row*kHW + q*8);
    }
}

// ---------------------------------------------------------------------------
// Attention: grid (32 i-tiles, 4 batches), block 256 (8 warps x 16 rows)
// ---------------------------------------------------------------------------
__global__ __launch_bounds__(256) void attn_mma(float* __restrict__ out)
{
    extern __shared__ char smem[];
    const uint32_t su = smem_u32(smem);
    uint32_t* s32 = reinterpret_cast<uint32_t*>(smem);
    const int tid = threadIdx.x, w = tid >> 5, lane = tid & 31;
    const int r0 = lane >> 2, qd = lane & 3;
    const int b = blockIdx.y, i0 = blockIdx.x * TI;
    const long pix0 = (long)b * kHW;

    // prologue: j-tile 0 via cp.async
    load_jtile(su, 0, pix0, b, 0, tid);
    CP_COMMIT();

    // YKi hi AND lo A-fragments resident (one-time gmem loads)
    uint32_t aH[8][4], aL[8][4];
    const unsigned short* ykbh = g_yk_h + (pix0 + i0 + w*16) * kC;
    const unsigned short* ykbl = g_yk_l + (pix0 + i0 + w*16) * kC;
    #pragma unroll
    for (int kb = 0; kb < 8; kb++) {
        int c0 = kb*16 + 2*qd;
        aH[kb][0] = *reinterpret_cast<const uint32_t*>(ykbh +  r0      *kC + c0);
        aH[kb][1] = *reinterpret_cast<const uint32_t*>(ykbh + (r0 + 8) *kC + c0);
        aH[kb][2] = *reinterpret_cast<const uint32_t*>(ykbh +  r0      *kC + c0 + 8);
        aH[kb][3] = *reinterpret_cast<const uint32_t*>(ykbh + (r0 + 8) *kC + c0 + 8);
        aL[kb][0] = *reinterpret_cast<const uint32_t*>(ykbl +  r0      *kC + c0);
        aL[kb][1] = *reinterpret_cast<const uint32_t*>(ykbl + (r0 + 8) *kC + c0);
        aL[kb][2] = *reinterpret_cast<const uint32_t*>(ykbl +  r0      *kC + c0 + 8);
        aL[kb][3] = *reinterpret_cast<const uint32_t*>(ykbl + (r0 + 8) *kC + c0 + 8);
    }

    float O[16][4];
    #pragma unroll
    for (int nt = 0; nt < 16; nt++)
        #pragma unroll
        for (int e = 0; e < 4; e++) O[nt][e] = 0.f;

    for (int j = 0; j < NJ; j++) {
        const int buf = j & 1;
        CP_WAIT0();
        __syncthreads();

        const uint32_t bb  = (uint32_t)(buf * BUF_BYTES) >> 2;
        const uint32_t xqh = bb + (XQH_OFF >> 2), xql = bb + (XQL_OFF >> 2);
        const uint32_t yth = bb + (YTH_OFF >> 2), ytl = bb + (YTL_OFF >> 2);

        // ---- prime S fragment pipeline FIRST (ahead of the cp.async burst) ----
        uint32_t fA[4], fB[4];
        ldfrag(fA, s32, xqh, xql, (uint32_t)r0*XQ_STR + qd);            // s=0: kb0,nt0
        ldfrag(fB, s32, xqh, xql, (uint32_t)(8 + r0)*XQ_STR + qd);      // s=1: kb0,nt1

        if (j + 1 < NJ) {
            load_jtile(su, buf ^ 1, pix0, b, (j + 1) * TJ, tid);
            CP_COMMIT();
        }

        // ---- S = YKi @ XQj^T (hh+hl+lh), 2-deep rolling prefetch ----
        float S[8][4];
        #pragma unroll
        for (int nt = 0; nt < 8; nt++)
            #pragma unroll
            for (int e = 0; e < 4; e++) S[nt][e] = 0.f;

        #pragma unroll
        for (int sp = 0; sp < 32; sp++) {
            const int s0 = 2*sp, s1 = 2*sp + 1;
            const int kb0 = s0 >> 3, nt0 = s0 & 7;
            const int kb1 = s1 >> 3, nt1 = s1 & 7;
            mma3(S[nt0], aH[kb0], aL[kb0], fA);
            if (s0 + 2 < 64) {
                const int k2 = (s0+2) >> 3, n2 = (s0+2) & 7;
                ldfrag(fA, s32, xqh, xql, (uint32_t)(8*n2 + r0)*XQ_STR + k2*8 + qd);
            }
            mma3(S[nt1], aH[kb1], aL[kb1], fB);
            if (s1 + 2 < 64) {
                const int k2 = (s1+2) >> 3, n2 = (s1+2) & 7;
                ldfrag(fB, s32, xqh, xql, (uint32_t)(8*n2 + r0)*XQ_STR + k2*8 + qd);
            }
        }

        // ---- prime PV fragments BEFORE sigmoid (latency hidden by MUFU/ALU) ----
        ldfrag(fA, s32, yth, ytl, (uint32_t)r0*YT_STR + qd);            // s=0: nt0,kb0
        ldfrag(fB, s32, yth, ytl, (uint32_t)r0*YT_STR + 8 + qd);        // s=1: nt0,kb1

        // ---- sigmoid (exact: EX2 + RCP) ----
        #pragma unroll
        for (int nt = 0; nt < 8; nt++)
            #pragma unroll
            for (int e = 0; e < 4; e++) {
                float ev = __expf(-S[nt][e]);
                S[nt][e] = __fdividef(1.f, 1.f + ev);
            }

        // ---- pack A-fragments (accumulator layout == A-operand layout) ----
        uint32_t aPh[4][4], aPl[4][4];
        #pragma unroll
        for (int kb = 0; kb < 4; kb++) {
            packHL(S[2*kb  ][0], S[2*kb  ][1], aPh[kb][0], aPl[kb][0]);
            packHL(S[2*kb  ][2], S[2*kb  ][3], aPh[kb][1], aPl[kb][1]);
            packHL(S[2*kb+1][0], S[2*kb+1][1], aPh[kb][2], aPl[kb][2]);
            packHL(S[2*kb+1][2], S[2*kb+1][3], aPh[kb][3], aPl[kb][3]);
        }

        // ---- O += A @ YKj (hh+hl+lh), 2-deep rolling prefetch ----
        #pragma unroll
        for (int sp = 0; sp < 32; sp++) {
            const int s0 = 2*sp, s1 = 2*sp + 1;
            const int nt0 = s0 >> 2, kb0 = s0 & 3;
            const int nt1 = s1 >> 2, kb1 = s1 & 3;
            mma3(O[nt0], aPh[kb0], aPl[kb0], fA);
            if (s0 + 2 < 64) {
                const int n2 = (s0+2) >> 2, k2 = (s0+2) & 3;
                ldfrag(fA, s32, yth, ytl, (uint32_t)(8*n2 + r0)*YT_STR + k2*8 + qd);
            }
            mma3(O[nt1], aPh[kb1], aPl[kb1], fB);
            if (s1 + 2 < 64) {
                const int n2 = (s1+2) >> 2, k2 = (s1+2) & 3;
                ldfrag(fB, s32, yth, ytl, (uint32_t)(8*n2 + r0)*YT_STR + k2*8 + qd);
            }
        }
    }

    // ---- epilogue: out = O + XQ (fp32 residual) ----
    const long rowbase = pix0 + i0 + w*16;
    #pragma unroll
    for (int nt = 0; nt < 16; nt++) {
        const int c = 8*nt + 2*qd;
        const long o0 = (rowbase + r0    ) * kC + c;
        const long o1 = (rowbase + r0 + 8) * kC + c;
        float2 q0 = *reinterpret_cast<const float2*>(g_xq + o0);
        float2 q1 = *reinterpret_cast<const float2*>(g_xq + o1);
        *reinterpret_cast<float2*>(out + o0) = make_float2(O[nt][0] + q0.x, O[nt][1] + q0.y);
        *reinterpret_cast<float2*>(out + o1) = make_float2(O[nt][2] + q1.x, O[nt][3] + q1.y);
    }
}

// ---------------------------------------------------------------------------
extern "C" void kernel_launch(void* const* d_in, const int* in_sizes, int n_in,
                              void* d_out, int out_size)
{
    const float* x  = (const float*)d_in[0];
    const float* y  = (const float*)d_in[1];
    const float* W1 = (const float*)d_in[2];
    const float* b1 = (const float*)d_in[3];
    const float* W2 = (const float*)d_in[4];
    const float* b2 = (const float*)d_in[5];

    cudaFuncSetAttribute(attn_mma, cudaFuncAttributeMaxDynamicSharedMemorySize, SMEM_TOTAL);

    proj_kernel<<<dim3(256, 2), 256>>>(x, y, W1, b1, W2, b2);
    attn_mma<<<dim3(32, 4), 256, SMEM_TOTAL>>>((float*)d_out);
}

// round 13
// speedup vs baseline: 1.1680x; 1.0038x over previous
#include <cuda_runtime.h>
#include <cuda_bf16.h>
#include <cstdint>

// ============================================================================
// out = sigmoid(YK @ XQ^T) @ YK + XQ ;  XQ = x@W1+b1, YK = y@W2+b2
// B=4, HW=4096, C=NF=128 fp32.
// mma.sync bf16 hi/lo split (hh+hl+lh). R13 = R12 resubmit (R12 bench died to
// the recurring infra-side "container failed twice" flake; kernel audit clean,
// and the R8->R9 resubmit precedent shows these are not kernel failures).
// 4-way ACCUMULATOR INTERLEAVING: MMAs issued pass-major over groups of 4
// accumulators so same-accumulator issue distance is 4 (covers HMMA RAW
// latency ~28cyc), with group-ahead fragment prefetch (~96cyc cover).
// ============================================================================

constexpr int kB = 4, kHW = 4096, kC = 128;
constexpr int TJ = 64, NJ = kHW / TJ;     // 64-wide j tiles
constexpr int TI = 128;

constexpr int XQ_STR = 68;   // 128 bf16 + 8 pad  (272 B/row)
constexpr int YT_STR = 36;   // 64 bf16 + 8 pad   (144 B/row)

constexpr int XQH_OFF = 0;                      // 64 x 272 = 17408 B
constexpr int XQL_OFF = 17408;
constexpr int YTH_OFF = 34816;                  // 128 x 144 = 18432 B
constexpr int YTL_OFF = 53248;
constexpr int BUF_BYTES = 71680;
constexpr int SMEM_TOTAL = 2 * BUF_BYTES;       // 143360 B

__device__ float          g_xq  [kB*kHW*kC];
__device__ unsigned short g_xq_h[kB*kHW*kC], g_xq_l[kB*kHW*kC];
__device__ unsigned short g_yk_h[kB*kHW*kC], g_yk_l[kB*kHW*kC];
__device__ unsigned short g_yt_h[kB*kHW*kC], g_yt_l[kB*kHW*kC];  // [b][feat][pix]

// ---------------------------------------------------------------------------
__device__ __forceinline__ uint32_t smem_u32(const void* p) {
    uint32_t a;
    asm("{ .reg .u64 t; cvta.to.shared.u64 t, %1; cvt.u32.u64 %0, t; }" : "=r"(a) : "l"(p));
    return a;
}
#define CP16(sm_addr, g_ptr) \
    asm volatile("cp.async.cg.shared.global [%0], [%1], 16;" \
        :: "r"(sm_addr), "l"(__cvta_generic_to_global(g_ptr)) : "memory")
#define CP_COMMIT() asm volatile("cp.async.commit_group;" ::: "memory")
#define CP_WAIT0()  asm volatile("cp.async.wait_group 0;" ::: "memory")

__device__ __forceinline__ void mma_bf16(float* d, const uint32_t* a,
                                         uint32_t b0, uint32_t b1) {
    asm volatile(
        "mma.sync.aligned.m16n8k16.row.col.f32.bf16.bf16.f32 "
        "{%0,%1,%2,%3}, {%4,%5,%6,%7}, {%8,%9}, {%0,%1,%2,%3};"
        : "+f"(d[0]), "+f"(d[1]), "+f"(d[2]), "+f"(d[3])
        : "r"(a[0]), "r"(a[1]), "r"(a[2]), "r"(a[3]), "r"(b0), "r"(b1));
}
__device__ __forceinline__ void packHL(float a0, float a1, uint32_t& hi, uint32_t& lo) {
    __nv_bfloat16 h0 = __float2bfloat16(a0), h1 = __float2bfloat16(a1);
    float l0 = a0 - __bfloat162float(h0);
    float l1 = a1 - __bfloat162float(h1);
    hi = (uint32_t)__bfloat16_as_ushort(h0) | ((uint32_t)__bfloat16_as_ushort(h1) << 16);
    asm("cvt.rn.bf16x2.f32 %0, %1, %2;" : "=r"(lo) : "f"(l1), "f"(l0));
}
__device__ __forceinline__ void ldfrag(uint32_t* f, const uint32_t* s32,
                                       uint32_t baseh, uint32_t basel, uint32_t bi) {
    f[0] = s32[baseh + bi]; f[1] = s32[baseh + bi + 4];
    f[2] = s32[basel + bi]; f[3] = s32[basel + bi + 4];
}

// load 4 B-fragment sets for S group (kb, g): rows 8*(4g+t)+r0, k-chunk kb
#define LD_SGROUP(f, kb, g) do {                                               \
    ldfrag((f)[0], s32, xqh, xql, (uint32_t)(8*((g)*4+0) + r0)*XQ_STR + (kb)*8 + qd); \
    ldfrag((f)[1], s32, xqh, xql, (uint32_t)(8*((g)*4+1) + r0)*XQ_STR + (kb)*8 + qd); \
    ldfrag((f)[2], s32, xqh, xql, (uint32_t)(8*((g)*4+2) + r0)*XQ_STR + (kb)*8 + qd); \
    ldfrag((f)[3], s32, xqh, xql, (uint32_t)(8*((g)*4+3) + r0)*XQ_STR + (kb)*8 + qd); \
} while (0)

// 12 MMAs pass-major over 4 accumulators (same-acc distance = 4)
#define S_MMAS(f, kb, g) do {                                                  \
    mma_bf16(S[(g)*4+0], aH[kb], (f)[0][0], (f)[0][1]);                        \
    mma_bf16(S[(g)*4+1], aH[kb], (f)[1][0], (f)[1][1]);                        \
    mma_bf16(S[(g)*4+2], aH[kb], (f)[2][0], (f)[2][1]);                        \
    mma_bf16(S[(g)*4+3], aH[kb], (f)[3][0], (f)[3][1]);                        \
    mma_bf16(S[(g)*4+0], aH[kb], (f)[0][2], (f)[0][3]);                        \
    mma_bf16(S[(g)*4+1], aH[kb], (f)[1][2], (f)[1][3]);                        \
    mma_bf16(S[(g)*4+2], aH[kb], (f)[2][2], (f)[2][3]);                        \
    mma_bf16(S[(g)*4+3], aH[kb], (f)[3][2], (f)[3][3]);                        \
    mma_bf16(S[(g)*4+0], aL[kb], (f)[0][0], (f)[0][1]);                        \
    mma_bf16(S[(g)*4+1], aL[kb], (f)[1][0], (f)[1][1]);                        \
    mma_bf16(S[(g)*4+2], aL[kb], (f)[2][0], (f)[2][1]);                        \
    mma_bf16(S[(g)*4+3], aL[kb], (f)[3][0], (f)[3][1]);                        \
} while (0)

// load 4 B-fragment sets for PV group (g, kb): rows 8*(4g+t)+r0, k-chunk kb
#define LD_PGROUP(f, g, kb) do {                                               \
    ldfrag((f)[0], s32, yth, ytl, (uint32_t)(8*((g)*4+0) + r0)*YT_STR + (kb)*8 + qd); \
    ldfrag((f)[1], s32, yth, ytl, (uint32_t)(8*((g)*4+1) + r0)*YT_STR + (kb)*8 + qd); \
    ldfrag((f)[2], s32, yth, ytl, (uint32_t)(8*((g)*4+2) + r0)*YT_STR + (kb)*8 + qd); \
    ldfrag((f)[3], s32, yth, ytl, (uint32_t)(8*((g)*4+3) + r0)*YT_STR + (kb)*8 + qd); \
} while (0)

#define P_MMAS(f, g, kb) do {                                                  \
    mma_bf16(O[(g)*4+0], aPh[kb], (f)[0][0], (f)[0][1]);                       \
    mma_bf16(O[(g)*4+1], aPh[kb], (f)[1][0], (f)[1][1]);                       \
    mma_bf16(O[(g)*4+2], aPh[kb], (f)[2][0], (f)[2][1]);                       \
    mma_bf16(O[(g)*4+3], aPh[kb], (f)[3][0], (f)[3][1]);                       \
    mma_bf16(O[(g)*4+0], aPh[kb], (f)[0][2], (f)[0][3]);                       \
    mma_bf16(O[(g)*4+1], aPh[kb], (f)[1][2], (f)[1][3]);                       \
    mma_bf16(O[(g)*4+2], aPh[kb], (f)[2][2], (f)[2][3]);                       \
    mma_bf16(O[(g)*4+3], aPh[kb], (f)[3][2], (f)[3][3]);                       \
    mma_bf16(O[(g)*4+0], aPl[kb], (f)[0][0], (f)[0][1]);                       \
    mma_bf16(O[(g)*4+1], aPl[kb], (f)[1][0], (f)[1][1]);                       \
    mma_bf16(O[(g)*4+2], aPl[kb], (f)[2][0], (f)[2][1]);                       \
    mma_bf16(O[(g)*4+3], aPl[kb], (f)[3][0], (f)[3][1]);                       \
} while (0)

// ---------------------------------------------------------------------------
// Projection (unchanged): XQ/YK fp32 + bf16 hi/lo splits + YK^T copy.
// ---------------------------------------------------------------------------
__global__ __launch_bounds__(256) void proj_kernel(
    const float* __restrict__ x,  const float* __restrict__ y,
    const float* __restrict__ W1, const float* __restrict__ b1,
    const float* __restrict__ W2, const float* __restrict__ b2)
{
    __shared__ float  xs[64][129];
    __shared__ float4 ws[16][32];

    const int which = blockIdx.y;
    const float* in   = which ? y  : x;
    const float* W    = which ? W2 : W1;
    const float* bias = which ? b2 : b1;

    const int base = blockIdx.x * 64;
    const int t = threadIdx.x, row = t & 63, fgrp = t >> 6, f0 = fgrp * 32;

    for (int v = t; v < 64*32; v += 256) {
        int r = v >> 5, c4 = v & 31;
        float4 d = reinterpret_cast<const float4*>(in + (long)(base + r)*kC)[c4];
        xs[r][c4*4+0]=d.x; xs[r][c4*4+1]=d.y; xs[r][c4*4+2]=d.z; xs[r][c4*4+3]=d.w;
    }
    float acc[32];
    #pragma unroll
    for (int i = 0; i < 32; i++) acc[i] = bias[f0 + i];

    for (int c0 = 0; c0 < kC; c0 += 16) {
        __syncthreads();
        for (int v = t; v < 16*32; v += 256) {
            int r = v >> 5, c4 = v & 31;
            ws[r][c4] = reinterpret_cast<const float4*>(W + (long)(c0 + r)*kC)[c4];
        }
        __syncthreads();
        #pragma unroll
        for (int cc = 0; cc < 16; cc++) {
            float xv = xs[row][c0 + cc];
            #pragma unroll
            for (int q = 0; q < 8; q++) {
                float4 w = ws[cc][fgrp*8 + q];
                acc[q*4+0] += xv*w.x; acc[q*4+1] += xv*w.y;
                acc[q*4+2] += xv*w.z; acc[q*4+3] += xv*w.w;
            }
        }
    }

    const int prow = base + row;
    unsigned short hs[32], ls[32];
    #pragma unroll
    for (int i = 0; i < 32; i++) {
        float v = acc[i];
        __nv_bfloat16 h = __float2bfloat16(v);
        float lf = v - __bfloat162float(h);
        hs[i] = __bfloat16_as_ushort(h);
        ls[i] = __bfloat16_as_ushort(__float2bfloat16(lf));
    }
    unsigned hw_[16], lw_[16];
    #pragma unroll
    for (int k = 0; k < 16; k++) {
        hw_[k] = (unsigned)hs[2*k] | ((unsigned)hs[2*k+1] << 16);
        lw_[k] = (unsigned)ls[2*k] | ((unsigned)ls[2*k+1] << 16);
    }
    const int u4base = prow * 16 + fgrp * 4;

    if (which == 0) {
        float* o = g_xq + (long)prow*kC + f0;
        #pragma unroll
        for (int q = 0; q < 8; q++)
            reinterpret_cast<float4*>(o)[q] =
                make_float4(acc[q*4+0], acc[q*4+1], acc[q*4+2], acc[q*4+3]);
        #pragma unroll
        for (int q = 0; q < 4; q++) {
            reinterpret_cast<uint4*>(g_xq_h)[u4base+q] = make_uint4(hw_[4*q],hw_[4*q+1],hw_[4*q+2],hw_[4*q+3]);
            reinterpret_cast<uint4*>(g_xq_l)[u4base+q] = make_uint4(lw_[4*q],lw_[4*q+1],lw_[4*q+2],lw_[4*q+3]);
        }
    } else {
        #pragma unroll
        for (int q = 0; q < 4; q++) {
            reinterpret_cast<uint4*>(g_yk_h)[u4base+q] = make_uint4(hw_[4*q],hw_[4*q+1],hw_[4*q+2],hw_[4*q+3]);
            reinterpret_cast<uint4*>(g_yk_l)[u4base+q] = make_uint4(lw_[4*q],lw_[4*q+1],lw_[4*q+2],lw_[4*q+3]);
        }
        const int bb = prow >> 12, pb = prow & 4095;
        #pragma unroll
        for (int i = 0; i < 32; i++) {
            int idx = (bb*kC + f0 + i)*kHW + pb;
            g_yt_h[idx] = hs[i];
            g_yt_l[idx] = ls[i];
        }
    }
}

// ---------------------------------------------------------------------------
// j-tile loader (unchanged)
// ---------------------------------------------------------------------------
__device__ __forceinline__ void load_jtile(uint32_t su, int buf, long pix0,
                                           int bIdx, int j0, int tid) {
    const uint32_t base = su + buf * BUF_BYTES;
    #pragma unroll
    for (int k = 0; k < 4; k++) {
        int idx = tid + k*256, row = idx >> 4, q = idx & 15;
        CP16(base + XQH_OFF + row*272 + q*16, g_xq_h + (pix0 + j0 + row)*kC + q*8);
        CP16(base + XQL_OFF + row*272 + q*16, g_xq_l + (pix0 + j0 + row)*kC + q*8);
    }
    const long ytb = (long)bIdx * kC * kHW + j0;
    #pragma unroll
    for (int k = 0; k < 4; k++) {
        int idx = tid + k*256, row = idx >> 3, q = idx & 7;
        CP16(base + YTH_OFF + row*144 + q*16, g_yt_h + ytb + (long)row*kHW + q*8);
        CP16(base + YTL_OFF + row*144 + q*16, g_yt_l + ytb + (long)row*kHW + q*8);
    }
}

// ---------------------------------------------------------------------------
// Attention: grid (32 i-tiles, 4 batches), block 256 (8 warps x 16 rows)
// ---------------------------------------------------------------------------
__global__ __launch_bounds__(256) void attn_mma(float* __restrict__ out)
{
    extern __shared__ char smem[];
    const uint32_t su = smem_u32(smem);
    uint32_t* s32 = reinterpret_cast<uint32_t*>(smem);
    const int tid = threadIdx.x, w = tid >> 5, lane = tid & 31;
    const int r0 = lane >> 2, qd = lane & 3;
    const int b = blockIdx.y, i0 = blockIdx.x * TI;
    const long pix0 = (long)b * kHW;

    load_jtile(su, 0, pix0, b, 0, tid);
    CP_COMMIT();

    // YKi hi AND lo A-fragments resident (one-time gmem loads)
    uint32_t aH[8][4], aL[8][4];
    const unsigned short* ykbh = g_yk_h + (pix0 + i0 + w*16) * kC;
    const unsigned short* ykbl = g_yk_l + (pix0 + i0 + w*16) * kC;
    #pragma unroll
    for (int kb = 0; kb < 8; kb++) {
        int c0 = kb*16 + 2*qd;
        aH[kb][0] = *reinterpret_cast<const uint32_t*>(ykbh +  r0      *kC + c0);
        aH[kb][1] = *reinterpret_cast<const uint32_t*>(ykbh + (r0 + 8) *kC + c0);
        aH[kb][2] = *reinterpret_cast<const uint32_t*>(ykbh +  r0      *kC + c0 + 8);
        aH[kb][3] = *reinterpret_cast<const uint32_t*>(ykbh + (r0 + 8) *kC + c0 + 8);
        aL[kb][0] = *reinterpret_cast<const uint32_t*>(ykbl +  r0      *kC + c0);
        aL[kb][1] = *reinterpret_cast<const uint32_t*>(ykbl + (r0 + 8) *kC + c0);
        aL[kb][2] = *reinterpret_cast<const uint32_t*>(ykbl +  r0      *kC + c0 + 8);
        aL[kb][3] = *reinterpret_cast<const uint32_t*>(ykbl + (r0 + 8) *kC + c0 + 8);
    }

    float O[16][4];
    #pragma unroll
    for (int nt = 0; nt < 16; nt++)
        #pragma unroll
        for (int e = 0; e < 4; e++) O[nt][e] = 0.f;

    for (int j = 0; j < NJ; j++) {
        const int buf = j & 1;
        CP_WAIT0();
        __syncthreads();

        const uint32_t bb  = (uint32_t)(buf * BUF_BYTES) >> 2;
        const uint32_t xqh = bb + (XQH_OFF >> 2), xql = bb + (XQL_OFF >> 2);
        const uint32_t yth = bb + (YTH_OFF >> 2), ytl = bb + (YTL_OFF >> 2);

        uint32_t fA[4][4], fB[4][4];
        // prime first S group ahead of the cp.async burst
        LD_SGROUP(fA, 0, 0);

        if (j + 1 < NJ) {
            load_jtile(su, buf ^ 1, pix0, b, (j + 1) * TJ, tid);
            CP_COMMIT();
        }

        // ---- S = YKi @ XQj^T, 4-way interleaved accumulators ----
        float S[8][4];
        #pragma unroll
        for (int nt = 0; nt < 8; nt++)
            #pragma unroll
            for (int e = 0; e < 4; e++) S[nt][e] = 0.f;

        #pragma unroll
        for (int kb = 0; kb < 8; kb++) {
            LD_SGROUP(fB, kb, 1);
            S_MMAS(fA, kb, 0);
            if (kb < 7) LD_SGROUP(fA, kb + 1, 0);
            S_MMAS(fB, kb, 1);
        }

        // ---- prime first PV group BEFORE sigmoid (latency hidden by MUFU) ----
        LD_PGROUP(fA, 0, 0);

        // ---- sigmoid (exact: EX2 + RCP) ----
        #pragma unroll
        for (int nt = 0; nt < 8; nt++)
            #pragma unroll
            for (int e = 0; e < 4; e++) {
                float ev = __expf(-S[nt][e]);
                S[nt][e] = __fdividef(1.f, 1.f + ev);
            }

        // ---- pack A-fragments (accumulator layout == A-operand layout) ----
        uint32_t aPh[4][4], aPl[4][4];
        #pragma unroll
        for (int kb = 0; kb < 4; kb++) {
            packHL(S[2*kb  ][0], S[2*kb  ][1], aPh[kb][0], aPl[kb][0]);
            packHL(S[2*kb  ][2], S[2*kb  ][3], aPh[kb][1], aPl[kb][1]);
            packHL(S[2*kb+1][0], S[2*kb+1][1], aPh[kb][2], aPl[kb][2]);
            packHL(S[2*kb+1][2], S[2*kb+1][3], aPh[kb][3], aPl[kb][3]);
        }

        // ---- O += A @ YKj, 4-way interleaved accumulators ----
        #pragma unroll
        for (int g = 0; g < 4; g++) {
            LD_PGROUP(fB, g, 1);
            P_MMAS(fA, g, 0);
            LD_PGROUP(fA, g, 2);
            P_MMAS(fB, g, 1);
            LD_PGROUP(fB, g, 3);
            P_MMAS(fA, g, 2);
            if (g < 3) LD_PGROUP(fA, g + 1, 0);
            P_MMAS(fB, g, 3);
        }
    }

    // ---- epilogue: out = O + XQ (fp32 residual) ----
    const long rowbase = pix0 + i0 + w*16;
    #pragma unroll
    for (int nt = 0; nt < 16; nt++) {
        const int c = 8*nt + 2*qd;
        const long o0 = (rowbase + r0    ) * kC + c;
        const long o1 = (rowbase + r0 + 8) * kC + c;
        float2 q0 = *reinterpret_cast<const float2*>(g_xq + o0);
        float2 q1 = *reinterpret_cast<const float2*>(g_xq + o1);
        *reinterpret_cast<float2*>(out + o0) = make_float2(O[nt][0] + q0.x, O[nt][1] + q0.y);
        *reinterpret_cast<float2*>(out + o1) = make_float2(O[nt][2] + q1.x, O[nt][3] + q1.y);
    }
}

// ---------------------------------------------------------------------------
extern "C" void kernel_launch(void* const* d_in, const int* in_sizes, int n_in,
                              void* d_out, int out_size)
{
    const float* x  = (const float*)d_in[0];
    const float* y  = (const float*)d_in[1];
    const float* W1 = (const float*)d_in[2];
    const float* b1 = (const float*)d_in[3];
    const float* W2 = (const float*)d_in[4];
    const float* b2 = (const float*)d_in[5];

    cudaFuncSetAttribute(attn_mma, cudaFuncAttributeMaxDynamicSharedMemorySize, SMEM_TOTAL);

    proj_kernel<<<dim3(256, 2), 256>>>(x, y, W1, b1, W2, b2);
    attn_mma<<<dim3(32, 4), 256, SMEM_TOTAL>>>((float*)d_out);
}

// round 14
// speedup vs baseline: 1.1682x; 1.0002x over previous
#include <cuda_runtime.h>
#include <cuda_bf16.h>
#include <cstdint>

// ============================================================================
// out = sigmoid(YK @ XQ^T) @ YK + XQ ;  XQ = x@W1+b1, YK = y@W2+b2
// B=4, HW=4096, C=NF=128 fp32.
// mma.sync bf16 hi/lo split (hh+hl+lh). R14: hide the sigmoid bubble.
// The 56-60% tensor plateau across R6-R13 = 6144 HMMA-cyc + ~2300 serial
// MUFU/pack cyc per SMSP per j-tile. Fix: S computed in two nt-groups;
// sigmoid+pack of group0 interleaved into group1's MMA stream; PV reordered
// kb-major with group1's sigmoid+pack interleaved into PV kb=0 (which only
// needs group0's packed fragments). Identical arithmetic -> same rel_err.
// ============================================================================

constexpr int kB = 4, kHW = 4096, kC = 128;
constexpr int TJ = 64, NJ = kHW / TJ;     // 64-wide j tiles
constexpr int TI = 128;

constexpr int XQ_STR = 68;   // 128 bf16 + 8 pad  (272 B/row)
constexpr int YT_STR = 36;   // 64 bf16 + 8 pad   (144 B/row)

constexpr int XQH_OFF = 0;                      // 64 x 272 = 17408 B
constexpr int XQL_OFF = 17408;
constexpr int YTH_OFF = 34816;                  // 128 x 144 = 18432 B
constexpr int YTL_OFF = 53248;
constexpr int BUF_BYTES = 71680;
constexpr int SMEM_TOTAL = 2 * BUF_BYTES;       // 143360 B

__device__ float          g_xq  [kB*kHW*kC];
__device__ unsigned short g_xq_h[kB*kHW*kC], g_xq_l[kB*kHW*kC];
__device__ unsigned short g_yk_h[kB*kHW*kC], g_yk_l[kB*kHW*kC];
__device__ unsigned short g_yt_h[kB*kHW*kC], g_yt_l[kB*kHW*kC];  // [b][feat][pix]

// ---------------------------------------------------------------------------
__device__ __forceinline__ uint32_t smem_u32(const void* p) {
    uint32_t a;
    asm("{ .reg .u64 t; cvta.to.shared.u64 t, %1; cvt.u32.u64 %0, t; }" : "=r"(a) : "l"(p));
    return a;
}
#define CP16(sm_addr, g_ptr) \
    asm volatile("cp.async.cg.shared.global [%0], [%1], 16;" \
        :: "r"(sm_addr), "l"(__cvta_generic_to_global(g_ptr)) : "memory")
#define CP_COMMIT() asm volatile("cp.async.commit_group;" ::: "memory")
#define CP_WAIT0()  asm volatile("cp.async.wait_group 0;" ::: "memory")

__device__ __forceinline__ void mma_bf16(float* d, const uint32_t* a,
                                         uint32_t b0, uint32_t b1) {
    asm volatile(
        "mma.sync.aligned.m16n8k16.row.col.f32.bf16.bf16.f32 "
        "{%0,%1,%2,%3}, {%4,%5,%6,%7}, {%8,%9}, {%0,%1,%2,%3};"
        : "+f"(d[0]), "+f"(d[1]), "+f"(d[2]), "+f"(d[3])
        : "r"(a[0]), "r"(a[1]), "r"(a[2]), "r"(a[3]), "r"(b0), "r"(b1));
}
__device__ __forceinline__ void packHL(float a0, float a1, uint32_t& hi, uint32_t& lo) {
    __nv_bfloat16 h0 = __float2bfloat16(a0), h1 = __float2bfloat16(a1);
    float l0 = a0 - __bfloat162float(h0);
    float l1 = a1 - __bfloat162float(h1);
    hi = (uint32_t)__bfloat16_as_ushort(h0) | ((uint32_t)__bfloat16_as_ushort(h1) << 16);
    asm("cvt.rn.bf16x2.f32 %0, %1, %2;" : "=r"(lo) : "f"(l1), "f"(l0));
}
__device__ __forceinline__ void ldfrag(uint32_t* f, const uint32_t* s32,
                                       uint32_t baseh, uint32_t basel, uint32_t bi) {
    f[0] = s32[baseh + bi]; f[1] = s32[baseh + bi + 4];
    f[2] = s32[basel + bi]; f[3] = s32[basel + bi + 4];
}

// load 4 B-fragment sets for S group (kb, g): rows 8*(4g+t)+r0, k-chunk kb
#define LD_SGROUP(f, kb, g) do {                                               \
    ldfrag((f)[0], s32, xqh, xql, (uint32_t)(8*((g)*4+0) + r0)*XQ_STR + (kb)*8 + qd); \
    ldfrag((f)[1], s32, xqh, xql, (uint32_t)(8*((g)*4+1) + r0)*XQ_STR + (kb)*8 + qd); \
    ldfrag((f)[2], s32, xqh, xql, (uint32_t)(8*((g)*4+2) + r0)*XQ_STR + (kb)*8 + qd); \
    ldfrag((f)[3], s32, xqh, xql, (uint32_t)(8*((g)*4+3) + r0)*XQ_STR + (kb)*8 + qd); \
} while (0)

// 12 MMAs pass-major over 4 accumulators (same-acc distance = 4)
#define S_MMAS(f, kb, g) do {                                                  \
    mma_bf16(S[(g)*4+0], aH[kb], (f)[0][0], (f)[0][1]);                        \
    mma_bf16(S[(g)*4+1], aH[kb], (f)[1][0], (f)[1][1]);                        \
    mma_bf16(S[(g)*4+2], aH[kb], (f)[2][0], (f)[2][1]);                        \
    mma_bf16(S[(g)*4+3], aH[kb], (f)[3][0], (f)[3][1]);                        \
    mma_bf16(S[(g)*4+0], aH[kb], (f)[0][2], (f)[0][3]);                        \
    mma_bf16(S[(g)*4+1], aH[kb], (f)[1][2], (f)[1][3]);                        \
    mma_bf16(S[(g)*4+2], aH[kb], (f)[2][2], (f)[2][3]);                        \
    mma_bf16(S[(g)*4+3], aH[kb], (f)[3][2], (f)[3][3]);                        \
    mma_bf16(S[(g)*4+0], aL[kb], (f)[0][0], (f)[0][1]);                        \
    mma_bf16(S[(g)*4+1], aL[kb], (f)[1][0], (f)[1][1]);                        \
    mma_bf16(S[(g)*4+2], aL[kb], (f)[2][0], (f)[2][1]);                        \
    mma_bf16(S[(g)*4+3], aL[kb], (f)[3][0], (f)[3][1]);                        \
} while (0)

// load 4 B-fragment sets for PV group (g, kb): rows 8*(4g+t)+r0, k-chunk kb
#define LD_PGROUP(f, g, kb) do {                                               \
    ldfrag((f)[0], s32, yth, ytl, (uint32_t)(8*((g)*4+0) + r0)*YT_STR + (kb)*8 + qd); \
    ldfrag((f)[1], s32, yth, ytl, (uint32_t)(8*((g)*4+1) + r0)*YT_STR + (kb)*8 + qd); \
    ldfrag((f)[2], s32, yth, ytl, (uint32_t)(8*((g)*4+2) + r0)*YT_STR + (kb)*8 + qd); \
    ldfrag((f)[3], s32, yth, ytl, (uint32_t)(8*((g)*4+3) + r0)*YT_STR + (kb)*8 + qd); \
} while (0)

#define P_MMAS(f, g, kb) do {                                                  \
    mma_bf16(O[(g)*4+0], aPh[kb], (f)[0][0], (f)[0][1]);                       \
    mma_bf16(O[(g)*4+1], aPh[kb], (f)[1][0], (f)[1][1]);                       \
    mma_bf16(O[(g)*4+2], aPh[kb], (f)[2][0], (f)[2][1]);                       \
    mma_bf16(O[(g)*4+3], aPh[kb], (f)[3][0], (f)[3][1]);                       \
    mma_bf16(O[(g)*4+0], aPh[kb], (f)[0][2], (f)[0][3]);                       \
    mma_bf16(O[(g)*4+1], aPh[kb], (f)[1][2], (f)[1][3]);                       \
    mma_bf16(O[(g)*4+2], aPh[kb], (f)[2][2], (f)[2][3]);                       \
    mma_bf16(O[(g)*4+3], aPh[kb], (f)[3][2], (f)[3][3]);                       \
    mma_bf16(O[(g)*4+0], aPl[kb], (f)[0][0], (f)[0][1]);                       \
    mma_bf16(O[(g)*4+1], aPl[kb], (f)[1][0], (f)[1][1]);                       \
    mma_bf16(O[(g)*4+2], aPl[kb], (f)[2][0], (f)[2][1]);                       \
    mma_bf16(O[(g)*4+3], aPl[kb], (f)[3][0], (f)[3][1]);                       \
} while (0)

// sigmoid + pack one pair: S row ntv, pair index p (even pair -> elems 0,1;
// odd pair -> elems 2,3). Destination mapping identical to R13's pack block.
#define SIGPACK(ntv, p) do {                                                   \
    const int _e0 = ((p) & 1) * 2;                                             \
    float _a0 = __fdividef(1.f, 1.f + __expf(-S[ntv][_e0]));                   \
    float _a1 = __fdividef(1.f, 1.f + __expf(-S[ntv][_e0 + 1]));               \
    packHL(_a0, _a1, aPh[(ntv) >> 1][((ntv) & 1) * 2 + ((p) & 1)],             \
                     aPl[(ntv) >> 1][((ntv) & 1) * 2 + ((p) & 1)]);            \
} while (0)

// ---------------------------------------------------------------------------
// Projection (unchanged): XQ/YK fp32 + bf16 hi/lo splits + YK^T copy.
// ---------------------------------------------------------------------------
__global__ __launch_bounds__(256) void proj_kernel(
    const float* __restrict__ x,  const float* __restrict__ y,
    const float* __restrict__ W1, const float* __restrict__ b1,
    const float* __restrict__ W2, const float* __restrict__ b2)
{
    __shared__ float  xs[64][129];
    __shared__ float4 ws[16][32];

    const int which = blockIdx.y;
    const float* in   = which ? y  : x;
    const float* W    = which ? W2 : W1;
    const float* bias = which ? b2 : b1;

    const int base = blockIdx.x * 64;
    const int t = threadIdx.x, row = t & 63, fgrp = t >> 6, f0 = fgrp * 32;

    for (int v = t; v < 64*32; v += 256) {
        int r = v >> 5, c4 = v & 31;
        float4 d = reinterpret_cast<const float4*>(in + (long)(base + r)*kC)[c4];
        xs[r][c4*4+0]=d.x; xs[r][c4*4+1]=d.y; xs[r][c4*4+2]=d.z; xs[r][c4*4+3]=d.w;
    }
    float acc[32];
    #pragma unroll
    for (int i = 0; i < 32; i++) acc[i] = bias[f0 + i];

    for (int c0 = 0; c0 < kC; c0 += 16) {
        __syncthreads();
        for (int v = t; v < 16*32; v += 256) {
            int r = v >> 5, c4 = v & 31;
            ws[r][c4] = reinterpret_cast<const float4*>(W + (long)(c0 + r)*kC)[c4];
        }
        __syncthreads();
        #pragma unroll
        for (int cc = 0; cc < 16; cc++) {
            float xv = xs[row][c0 + cc];
            #pragma unroll
            for (int q = 0; q < 8; q++) {
                float4 w = ws[cc][fgrp*8 + q];
                acc[q*4+0] += xv*w.x; acc[q*4+1] += xv*w.y;
                acc[q*4+2] += xv*w.z; acc[q*4+3] += xv*w.w;
            }
        }
    }

    const int prow = base + row;
    unsigned short hs[32], ls[32];
    #pragma unroll
    for (int i = 0; i < 32; i++) {
        float v = acc[i];
        __nv_bfloat16 h = __float2bfloat16(v);
        float lf = v - __bfloat162float(h);
        hs[i] = __bfloat16_as_ushort(h);
        ls[i] = __bfloat16_as_ushort(__float2bfloat16(lf));
    }
    unsigned hw_[16], lw_[16];
    #pragma unroll
    for (int k = 0; k < 16; k++) {
        hw_[k] = (unsigned)hs[2*k] | ((unsigned)hs[2*k+1] << 16);
        lw_[k] = (unsigned)ls[2*k] | ((unsigned)ls[2*k+1] << 16);
    }
    const int u4base = prow * 16 + fgrp * 4;

    if (which == 0) {
        float* o = g_xq + (long)prow*kC + f0;
        #pragma unroll
        for (int q = 0; q < 8; q++)
            reinterpret_cast<float4*>(o)[q] =
                make_float4(acc[q*4+0], acc[q*4+1], acc[q*4+2], acc[q*4+3]);
        #pragma unroll
        for (int q = 0; q < 4; q++) {
            reinterpret_cast<uint4*>(g_xq_h)[u4base+q] = make_uint4(hw_[4*q],hw_[4*q+1],hw_[4*q+2],hw_[4*q+3]);
            reinterpret_cast<uint4*>(g_xq_l)[u4base+q] = make_uint4(lw_[4*q],lw_[4*q+1],lw_[4*q+2],lw_[4*q+3]);
        }
    } else {
        #pragma unroll
        for (int q = 0; q < 4; q++) {
            reinterpret_cast<uint4*>(g_yk_h)[u4base+q] = make_uint4(hw_[4*q],hw_[4*q+1],hw_[4*q+2],hw_[4*q+3]);
            reinterpret_cast<uint4*>(g_yk_l)[u4base+q] = make_uint4(lw_[4*q],lw_[4*q+1],lw_[4*q+2],lw_[4*q+3]);
        }
        const int bb = prow >> 12, pb = prow & 4095;
        #pragma unroll
        for (int i = 0; i < 32; i++) {
            int idx = (bb*kC + f0 + i)*kHW + pb;
            g_yt_h[idx] = hs[i];
            g_yt_l[idx] = ls[i];
        }
    }
}

// ---------------------------------------------------------------------------
// j-tile loader (unchanged)
// ---------------------------------------------------------------------------
__device__ __forceinline__ void load_jtile(uint32_t su, int buf, long pix0,
                                           int bIdx, int j0, int tid) {
    const uint32_t base = su + buf * BUF_BYTES;
    #pragma unroll
    for (int k = 0; k < 4; k++) {
        int idx = tid + k*256, row = idx >> 4, q = idx & 15;
        CP16(base + XQH_OFF + row*272 + q*16, g_xq_h + (pix0 + j0 + row)*kC + q*8);
        CP16(base + XQL_OFF + row*272 + q*16, g_xq_l + (pix0 + j0 + row)*kC + q*8);
    }
    const long ytb = (long)bIdx * kC * kHW + j0;
    #pragma unroll
    for (int k = 0; k < 4; k++) {
        int idx = tid + k*256, row = idx >> 3, q = idx & 7;
        CP16(base + YTH_OFF + row*144 + q*16, g_yt_h + ytb + (long)row*kHW + q*8);
        CP16(base + YTL_OFF + row*144 + q*16, g_yt_l + ytb + (long)row*kHW + q*8);
    }
}

// ---------------------------------------------------------------------------
// Attention: grid (32 i-tiles, 4 batches), block 256 (8 warps x 16 rows)
// ---------------------------------------------------------------------------
__global__ __launch_bounds__(256) void attn_mma(float* __restrict__ out)
{
    extern __shared__ char smem[];
    const uint32_t su = smem_u32(smem);
    uint32_t* s32 = reinterpret_cast<uint32_t*>(smem);
    const int tid = threadIdx.x, w = tid >> 5, lane = tid & 31;
    const int r0 = lane >> 2, qd = lane & 3;
    const int b = blockIdx.y, i0 = blockIdx.x * TI;
    const long pix0 = (long)b * kHW;

    load_jtile(su, 0, pix0, b, 0, tid);
    CP_COMMIT();

    // YKi hi AND lo A-fragments resident (one-time gmem loads)
    uint32_t aH[8][4], aL[8][4];
    const unsigned short* ykbh = g_yk_h + (pix0 + i0 + w*16) * kC;
    const unsigned short* ykbl = g_yk_l + (pix0 + i0 + w*16) * kC;
    #pragma unroll
    for (int kb = 0; kb < 8; kb++) {
        int c0 = kb*16 + 2*qd;
        aH[kb][0] = *reinterpret_cast<const uint32_t*>(ykbh +  r0      *kC + c0);
        aH[kb][1] = *reinterpret_cast<const uint32_t*>(ykbh + (r0 + 8) *kC + c0);
        aH[kb][2] = *reinterpret_cast<const uint32_t*>(ykbh +  r0      *kC + c0 + 8);
        aH[kb][3] = *reinterpret_cast<const uint32_t*>(ykbh + (r0 + 8) *kC + c0 + 8);
        aL[kb][0] = *reinterpret_cast<const uint32_t*>(ykbl +  r0      *kC + c0);
        aL[kb][1] = *reinterpret_cast<const uint32_t*>(ykbl + (r0 + 8) *kC + c0);
        aL[kb][2] = *reinterpret_cast<const uint32_t*>(ykbl +  r0      *kC + c0 + 8);
        aL[kb][3] = *reinterpret_cast<const uint32_t*>(ykbl + (r0 + 8) *kC + c0 + 8);
    }

    float O[16][4];
    #pragma unroll
    for (int nt = 0; nt < 16; nt++)
        #pragma unroll
        for (int e = 0; e < 4; e++) O[nt][e] = 0.f;

    for (int j = 0; j < NJ; j++) {
        const int buf = j & 1;
        CP_WAIT0();
        __syncthreads();

        const uint32_t bb  = (uint32_t)(buf * BUF_BYTES) >> 2;
        const uint32_t xqh = bb + (XQH_OFF >> 2), xql = bb + (XQL_OFF >> 2);
        const uint32_t yth = bb + (YTH_OFF >> 2), ytl = bb + (YTL_OFF >> 2);

        uint32_t fA[4][4], fB[4][4];
        LD_SGROUP(fA, 0, 0);      // prime ahead of the cp.async burst

        if (j + 1 < NJ) {
            load_jtile(su, buf ^ 1, pix0, b, (j + 1) * TJ, tid);
            CP_COMMIT();
        }

        float S[8][4];
        #pragma unroll
        for (int nt = 0; nt < 8; nt++)
            #pragma unroll
            for (int e = 0; e < 4; e++) S[nt][e] = 0.f;

        // ---- S group 0 (rows 0..3), kb-major ----
        #pragma unroll
        for (int kk = 0; kk < 4; kk++) {
            LD_SGROUP(fB, 2*kk + 1, 0);
            S_MMAS(fA, 2*kk, 0);
            if (kk < 3) LD_SGROUP(fA, 2*kk + 2, 0);
            S_MMAS(fB, 2*kk + 1, 0);
        }

        // ---- S group 1 (rows 4..7) with group-0 sigmoid/pack interleaved ----
        uint32_t aPh[4][4], aPl[4][4];
        LD_SGROUP(fA, 0, 1);
        #pragma unroll
        for (int kk = 0; kk < 4; kk++) {
            LD_SGROUP(fB, 2*kk + 1, 1);
            SIGPACK(kk, 2*kk);               // pair 2kk  -> row kk, elems 0,1
            S_MMAS(fA, 2*kk, 1);
            if (kk < 3) LD_SGROUP(fA, 2*kk + 2, 1);
            SIGPACK(kk, 2*kk + 1);           // pair 2kk+1 -> row kk, elems 2,3
            S_MMAS(fB, 2*kk + 1, 1);
        }

        // ---- PV, kb-major; group-1 sigmoid/pack interleaved into kb=0 ----
        LD_PGROUP(fA, 0, 0);
        // kb = 0 (uses aPh/aPl[0], produced from group 0)
        LD_PGROUP(fB, 1, 0);  SIGPACK(4, 0); SIGPACK(4, 1); P_MMAS(fA, 0, 0);
        LD_PGROUP(fA, 2, 0);  SIGPACK(5, 2); SIGPACK(5, 3); P_MMAS(fB, 1, 0);
        LD_PGROUP(fB, 3, 0);  SIGPACK(6, 4); SIGPACK(6, 5); P_MMAS(fA, 2, 0);
        LD_PGROUP(fA, 0, 1);  SIGPACK(7, 6); SIGPACK(7, 7); P_MMAS(fB, 3, 0);
        // kb = 1
        LD_PGROUP(fB, 1, 1);  P_MMAS(fA, 0, 1);
        LD_PGROUP(fA, 2, 1);  P_MMAS(fB, 1, 1);
        LD_PGROUP(fB, 3, 1);  P_MMAS(fA, 2, 1);
        LD_PGROUP(fA, 0, 2);  P_MMAS(fB, 3, 1);
        // kb = 2 (uses aPh/aPl[2], produced during kb=0 block)
        LD_PGROUP(fB, 1, 2);  P_MMAS(fA, 0, 2);
        LD_PGROUP(fA, 2, 2);  P_MMAS(fB, 1, 2);
        LD_PGROUP(fB, 3, 2);  P_MMAS(fA, 2, 2);
        LD_PGROUP(fA, 0, 3);  P_MMAS(fB, 3, 2);
        // kb = 3
        LD_PGROUP(fB, 1, 3);  P_MMAS(fA, 0, 3);
        LD_PGROUP(fA, 2, 3);  P_MMAS(fB, 1, 3);
        LD_PGROUP(fB, 3, 3);  P_MMAS(fA, 2, 3);
        P_MMAS(fB, 3, 3);
    }

    // ---- epilogue: out = O + XQ (fp32 residual) ----
    const long rowbase = pix0 + i0 + w*16;
    #pragma unroll
    for (int nt = 0; nt < 16; nt++) {
        const int c = 8*nt + 2*qd;
        const long o0 = (rowbase + r0    ) * kC + c;
        const long o1 = (rowbase + r0 + 8) * kC + c;
        float2 q0 = *reinterpret_cast<const float2*>(g_xq + o0);
        float2 q1 = *reinterpret_cast<const float2*>(g_xq + o1);
        *reinterpret_cast<float2*>(out + o0) = make_float2(O[nt][0] + q0.x, O[nt][1] + q0.y);
        *reinterpret_cast<float2*>(out + o1) = make_float2(O[nt][2] + q1.x, O[nt][3] + q1.y);
    }
}

// ---------------------------------------------------------------------------
extern "C" void kernel_launch(void* const* d_in, const int* in_sizes, int n_in,
                              void* d_out, int out_size)
{
    const float* x  = (const float*)d_in[0];
    const float* y  = (const float*)d_in[1];
    const float* W1 = (const float*)d_in[2];
    const float* b1 = (const float*)d_in[3];
    const float* W2 = (const float*)d_in[4];
    const float* b2 = (const float*)d_in[5];

    cudaFuncSetAttribute(attn_mma, cudaFuncAttributeMaxDynamicSharedMemorySize, SMEM_TOTAL);

    proj_kernel<<<dim3(256, 2), 256>>>(x, y, W1, b1, W2, b2);
    attn_mma<<<dim3(32, 4), 256, SMEM_TOTAL>>>((float*)d_out);
}

// round 15
// speedup vs baseline: 1.2099x; 1.0357x over previous
#include <cuda_runtime.h>
#include <cuda_bf16.h>
#include <cstdint>

// ============================================================================
// out = sigmoid(YK @ XQ^T) @ YK + XQ ;  XQ = x@W1+b1, YK = y@W2+b2
// B=4, HW=4096, C=NF=128 fp32.
// mma.sync bf16 hi/lo split (hh+hl+lh). R15 = R13 with B-fragment loads via
// ldmatrix.x4 (1 instr replaces 4 LDS.32): tensor+L1 ~ 101% across R6-R14
// says tensor and MIO serialize; LDS instr count per SM per j-tile drops
// 4096 -> 1024 (bytes unchanged). Identical arithmetic -> same rel_err.
// ============================================================================

constexpr int kB = 4, kHW = 4096, kC = 128;
constexpr int TJ = 64, NJ = kHW / TJ;     // 64-wide j tiles
constexpr int TI = 128;

constexpr int XQ_STR = 68;   // 128 bf16 + 8 pad  (272 B/row)
constexpr int YT_STR = 36;   // 64 bf16 + 8 pad   (144 B/row)

constexpr int XQH_OFF = 0;                      // 64 x 272 = 17408 B
constexpr int XQL_OFF = 17408;
constexpr int YTH_OFF = 34816;                  // 128 x 144 = 18432 B
constexpr int YTL_OFF = 53248;
constexpr int BUF_BYTES = 71680;
constexpr int SMEM_TOTAL = 2 * BUF_BYTES;       // 143360 B

__device__ float          g_xq  [kB*kHW*kC];
__device__ unsigned short g_xq_h[kB*kHW*kC], g_xq_l[kB*kHW*kC];
__device__ unsigned short g_yk_h[kB*kHW*kC], g_yk_l[kB*kHW*kC];
__device__ unsigned short g_yt_h[kB*kHW*kC], g_yt_l[kB*kHW*kC];  // [b][feat][pix]

// ---------------------------------------------------------------------------
__device__ __forceinline__ uint32_t smem_u32(const void* p) {
    uint32_t a;
    asm("{ .reg .u64 t; cvta.to.shared.u64 t, %1; cvt.u32.u64 %0, t; }" : "=r"(a) : "l"(p));
    return a;
}
#define CP16(sm_addr, g_ptr) \
    asm volatile("cp.async.cg.shared.global [%0], [%1], 16;" \
        :: "r"(sm_addr), "l"(__cvta_generic_to_global(g_ptr)) : "memory")
#define CP_COMMIT() asm volatile("cp.async.commit_group;" ::: "memory")
#define CP_WAIT0()  asm volatile("cp.async.wait_group 0;" ::: "memory")

__device__ __forceinline__ void mma_bf16(float* d, const uint32_t* a,
                                         uint32_t b0, uint32_t b1) {
    asm volatile(
        "mma.sync.aligned.m16n8k16.row.col.f32.bf16.bf16.f32 "
        "{%0,%1,%2,%3}, {%4,%5,%6,%7}, {%8,%9}, {%0,%1,%2,%3};"
        : "+f"(d[0]), "+f"(d[1]), "+f"(d[2]), "+f"(d[3])
        : "r"(a[0]), "r"(a[1]), "r"(a[2]), "r"(a[3]), "r"(b0), "r"(b1));
}
__device__ __forceinline__ void packHL(float a0, float a1, uint32_t& hi, uint32_t& lo) {
    __nv_bfloat16 h0 = __float2bfloat16(a0), h1 = __float2bfloat16(a1);
    float l0 = a0 - __bfloat162float(h0);
    float l1 = a1 - __bfloat162float(h1);
    hi = (uint32_t)__bfloat16_as_ushort(h0) | ((uint32_t)__bfloat16_as_ushort(h1) << 16);
    asm("cvt.rn.bf16x2.f32 %0, %1, %2;" : "=r"(lo) : "f"(l1), "f"(l0));
}

// One ldmatrix.x4 = {b0_hi, b1_hi, b0_lo, b1_lo} for one 8-row n-group,
// one 16-wide k-chunk. Lane groups 0-7/8-15/16-23/24-31 address hi-klo /
// hi-khi / lo-klo / lo-khi rows respectively (per-lane base precomputed).
#define LDM4(f, a)                                                             \
    asm volatile("ldmatrix.sync.aligned.m8n8.x4.shared.b16 {%0,%1,%2,%3}, [%4];" \
        : "=r"((f)[0]), "=r"((f)[1]), "=r"((f)[2]), "=r"((f)[3]) : "r"(a))

// load 4 fragment sets for S group (kb, g): nt = 4g+0..3
#define LD_SGROUP(f, kb, g) do {                                               \
    LDM4((f)[0], bufS + (uint32_t)((8*((g)*4+0)*XQ_STR + (kb)*8) << 2));       \
    LDM4((f)[1], bufS + (uint32_t)((8*((g)*4+1)*XQ_STR + (kb)*8) << 2));       \
    LDM4((f)[2], bufS + (uint32_t)((8*((g)*4+2)*XQ_STR + (kb)*8) << 2));       \
    LDM4((f)[3], bufS + (uint32_t)((8*((g)*4+3)*XQ_STR + (kb)*8) << 2));       \
} while (0)

// 12 MMAs pass-major over 4 accumulators (same-acc distance = 4)
#define S_MMAS(f, kb, g) do {                                                  \
    mma_bf16(S[(g)*4+0], aH[kb], (f)[0][0], (f)[0][1]);                        \
    mma_bf16(S[(g)*4+1], aH[kb], (f)[1][0], (f)[1][1]);                        \
    mma_bf16(S[(g)*4+2], aH[kb], (f)[2][0], (f)[2][1]);                        \
    mma_bf16(S[(g)*4+3], aH[kb], (f)[3][0], (f)[3][1]);                        \
    mma_bf16(S[(g)*4+0], aH[kb], (f)[0][2], (f)[0][3]);                        \
    mma_bf16(S[(g)*4+1], aH[kb], (f)[1][2], (f)[1][3]);                        \
    mma_bf16(S[(g)*4+2], aH[kb], (f)[2][2], (f)[2][3]);                        \
    mma_bf16(S[(g)*4+3], aH[kb], (f)[3][2], (f)[3][3]);                        \
    mma_bf16(S[(g)*4+0], aL[kb], (f)[0][0], (f)[0][1]);                        \
    mma_bf16(S[(g)*4+1], aL[kb], (f)[1][0], (f)[1][1]);                        \
    mma_bf16(S[(g)*4+2], aL[kb], (f)[2][0], (f)[2][1]);                        \
    mma_bf16(S[(g)*4+3], aL[kb], (f)[3][0], (f)[3][1]);                        \
} while (0)

// load 4 fragment sets for PV group (g, kb): nt = 4g+0..3
#define LD_PGROUP(f, g, kb) do {                                               \
    LDM4((f)[0], bufP + (uint32_t)((8*((g)*4+0)*YT_STR + (kb)*8) << 2));       \
    LDM4((f)[1], bufP + (uint32_t)((8*((g)*4+1)*YT_STR + (kb)*8) << 2));       \
    LDM4((f)[2], bufP + (uint32_t)((8*((g)*4+2)*YT_STR + (kb)*8) << 2));       \
    LDM4((f)[3], bufP + (uint32_t)((8*((g)*4+3)*YT_STR + (kb)*8) << 2));       \
} while (0)

#define P_MMAS(f, g, kb) do {                                                  \
    mma_bf16(O[(g)*4+0], aPh[kb], (f)[0][0], (f)[0][1]);                       \
    mma_bf16(O[(g)*4+1], aPh[kb], (f)[1][0], (f)[1][1]);                       \
    mma_bf16(O[(g)*4+2], aPh[kb], (f)[2][0], (f)[2][1]);                       \
    mma_bf16(O[(g)*4+3], aPh[kb], (f)[3][0], (f)[3][1]);                       \
    mma_bf16(O[(g)*4+0], aPh[kb], (f)[0][2], (f)[0][3]);                       \
    mma_bf16(O[(g)*4+1], aPh[kb], (f)[1][2], (f)[1][3]);                       \
    mma_bf16(O[(g)*4+2], aPh[kb], (f)[2][2], (f)[2][3]);                       \
    mma_bf16(O[(g)*4+3], aPh[kb], (f)[3][2], (f)[3][3]);                       \
    mma_bf16(O[(g)*4+0], aPl[kb], (f)[0][0], (f)[0][1]);                       \
    mma_bf16(O[(g)*4+1], aPl[kb], (f)[1][0], (f)[1][1]);                       \
    mma_bf16(O[(g)*4+2], aPl[kb], (f)[2][0], (f)[2][1]);                       \
    mma_bf16(O[(g)*4+3], aPl[kb], (f)[3][0], (f)[3][1]);                       \
} while (0)

// ---------------------------------------------------------------------------
// Projection (unchanged): XQ/YK fp32 + bf16 hi/lo splits + YK^T copy.
// ---------------------------------------------------------------------------
__global__ __launch_bounds__(256) void proj_kernel(
    const float* __restrict__ x,  const float* __restrict__ y,
    const float* __restrict__ W1, const float* __restrict__ b1,
    const float* __restrict__ W2, const float* __restrict__ b2)
{
    __shared__ float  xs[64][129];
    __shared__ float4 ws[16][32];

    const int which = blockIdx.y;
    const float* in   = which ? y  : x;
    const float* W    = which ? W2 : W1;
    const float* bias = which ? b2 : b1;

    const int base = blockIdx.x * 64;
    const int t = threadIdx.x, row = t & 63, fgrp = t >> 6, f0 = fgrp * 32;

    for (int v = t; v < 64*32; v += 256) {
        int r = v >> 5, c4 = v & 31;
        float4 d = reinterpret_cast<const float4*>(in + (long)(base + r)*kC)[c4];
        xs[r][c4*4+0]=d.x; xs[r][c4*4+1]=d.y; xs[r][c4*4+2]=d.z; xs[r][c4*4+3]=d.w;
    }
    float acc[32];
    #pragma unroll
    for (int i = 0; i < 32; i++) acc[i] = bias[f0 + i];

    for (int c0 = 0; c0 < kC; c0 += 16) {
        __syncthreads();
        for (int v = t; v < 16*32; v += 256) {
            int r = v >> 5, c4 = v & 31;
            ws[r][c4] = reinterpret_cast<const float4*>(W + (long)(c0 + r)*kC)[c4];
        }
        __syncthreads();
        #pragma unroll
        for (int cc = 0; cc < 16; cc++) {
            float xv = xs[row][c0 + cc];
            #pragma unroll
            for (int q = 0; q < 8; q++) {
                float4 w = ws[cc][fgrp*8 + q];
                acc[q*4+0] += xv*w.x; acc[q*4+1] += xv*w.y;
                acc[q*4+2] += xv*w.z; acc[q*4+3] += xv*w.w;
            }
        }
    }

    const int prow = base + row;
    unsigned short hs[32], ls[32];
    #pragma unroll
    for (int i = 0; i < 32; i++) {
        float v = acc[i];
        __nv_bfloat16 h = __float2bfloat16(v);
        float lf = v - __bfloat162float(h);
        hs[i] = __bfloat16_as_ushort(h);
        ls[i] = __bfloat16_as_ushort(__float2bfloat16(lf));
    }
    unsigned hw_[16], lw_[16];
    #pragma unroll
    for (int k = 0; k < 16; k++) {
        hw_[k] = (unsigned)hs[2*k] | ((unsigned)hs[2*k+1] << 16);
        lw_[k] = (unsigned)ls[2*k] | ((unsigned)ls[2*k+1] << 16);
    }
    const int u4base = prow * 16 + fgrp * 4;

    if (which == 0) {
        float* o = g_xq + (long)prow*kC + f0;
        #pragma unroll
        for (int q = 0; q < 8; q++)
            reinterpret_cast<float4*>(o)[q] =
                make_float4(acc[q*4+0], acc[q*4+1], acc[q*4+2], acc[q*4+3]);
        #pragma unroll
        for (int q = 0; q < 4; q++) {
            reinterpret_cast<uint4*>(g_xq_h)[u4base+q] = make_uint4(hw_[4*q],hw_[4*q+1],hw_[4*q+2],hw_[4*q+3]);
            reinterpret_cast<uint4*>(g_xq_l)[u4base+q] = make_uint4(lw_[4*q],lw_[4*q+1],lw_[4*q+2],lw_[4*q+3]);
        }
    } else {
        #pragma unroll
        for (int q = 0; q < 4; q++) {
            reinterpret_cast<uint4*>(g_yk_h)[u4base+q] = make_uint4(hw_[4*q],hw_[4*q+1],hw_[4*q+2],hw_[4*q+3]);
            reinterpret_cast<uint4*>(g_yk_l)[u4base+q] = make_uint4(lw_[4*q],lw_[4*q+1],lw_[4*q+2],lw_[4*q+3]);
        }
        const int bb = prow >> 12, pb = prow & 4095;
        #pragma unroll
        for (int i = 0; i < 32; i++) {
            int idx = (bb*kC + f0 + i)*kHW + pb;
            g_yt_h[idx] = hs[i];
            g_yt_l[idx] = ls[i];
        }
    }
}

// ---------------------------------------------------------------------------
// j-tile loader (unchanged)
// ---------------------------------------------------------------------------
__device__ __forceinline__ void load_jtile(uint32_t su, int buf, long pix0,
                                           int bIdx, int j0, int tid) {
    const uint32_t base = su + buf * BUF_BYTES;
    #pragma unroll
    for (int k = 0; k < 4; k++) {
        int idx = tid + k*256, row = idx >> 4, q = idx & 15;
        CP16(base + XQH_OFF + row*272 + q*16, g_xq_h + (pix0 + j0 + row)*kC + q*8);
        CP16(base + XQL_OFF + row*272 + q*16, g_xq_l + (pix0 + j0 + row)*kC + q*8);
    }
    const long ytb = (long)bIdx * kC * kHW + j0;
    #pragma unroll
    for (int k = 0; k < 4; k++) {
        int idx = tid + k*256, row = idx >> 3, q = idx & 7;
        CP16(base + YTH_OFF + row*144 + q*16, g_yt_h + ytb + (long)row*kHW + q*8);
        CP16(base + YTL_OFF + row*144 + q*16, g_yt_l + ytb + (long)row*kHW + q*8);
    }
}

// ---------------------------------------------------------------------------
// Attention: grid (32 i-tiles, 4 batches), block 256 (8 warps x 16 rows)
// ---------------------------------------------------------------------------
__global__ __launch_bounds__(256) void attn_mma(float* __restrict__ out)
{
    extern __shared__ char smem[];
    const uint32_t su = smem_u32(smem);
    const int tid = threadIdx.x, w = tid >> 5, lane = tid & 31;
    const int r0 = lane >> 2, qd = lane & 3;
    const int b = blockIdx.y, i0 = blockIdx.x * TI;
    const long pix0 = (long)b * kHW;

    // per-lane ldmatrix base offsets (bytes, within a buffer):
    // lane 0-7: hi rows k-lo | 8-15: hi rows k-hi | 16-23: lo k-lo | 24-31: lo k-hi
    const int li8 = lane & 7, seg = (lane >> 3) & 1, hlo = lane >> 4;
    const uint32_t sOffL = (uint32_t)(hlo ? XQL_OFF : XQH_OFF)
                         + ((uint32_t)(li8*XQ_STR + seg*4) << 2);
    const uint32_t pOffL = (uint32_t)(hlo ? YTL_OFF : YTH_OFF)
                         + ((uint32_t)(li8*YT_STR + seg*4) << 2);

    load_jtile(su, 0, pix0, b, 0, tid);
    CP_COMMIT();

    // YKi hi AND lo A-fragments resident (one-time gmem loads)
    uint32_t aH[8][4], aL[8][4];
    const unsigned short* ykbh = g_yk_h + (pix0 + i0 + w*16) * kC;
    const unsigned short* ykbl = g_yk_l + (pix0 + i0 + w*16) * kC;
    #pragma unroll
    for (int kb = 0; kb < 8; kb++) {
        int c0 = kb*16 + 2*qd;
        aH[kb][0] = *reinterpret_cast<const uint32_t*>(ykbh +  r0      *kC + c0);
        aH[kb][1] = *reinterpret_cast<const uint32_t*>(ykbh + (r0 + 8) *kC + c0);
        aH[kb][2] = *reinterpret_cast<const uint32_t*>(ykbh +  r0      *kC + c0 + 8);
        aH[kb][3] = *reinterpret_cast<const uint32_t*>(ykbh + (r0 + 8) *kC + c0 + 8);
        aL[kb][0] = *reinterpret_cast<const uint32_t*>(ykbl +  r0      *kC + c0);
        aL[kb][1] = *reinterpret_cast<const uint32_t*>(ykbl + (r0 + 8) *kC + c0);
        aL[kb][2] = *reinterpret_cast<const uint32_t*>(ykbl +  r0      *kC + c0 + 8);
        aL[kb][3] = *reinterpret_cast<const uint32_t*>(ykbl + (r0 + 8) *kC + c0 + 8);
    }

    float O[16][4];
    #pragma unroll
    for (int nt = 0; nt < 16; nt++)
        #pragma unroll
        for (int e = 0; e < 4; e++) O[nt][e] = 0.f;

    for (int j = 0; j < NJ; j++) {
        const int buf = j & 1;
        CP_WAIT0();
        __syncthreads();

        const uint32_t bufbyte = su + (uint32_t)(buf * BUF_BYTES);
        const uint32_t bufS = bufbyte + sOffL;
        const uint32_t bufP = bufbyte + pOffL;

        uint32_t fA[4][4], fB[4][4];
        LD_SGROUP(fA, 0, 0);      // prime ahead of the cp.async burst

        if (j + 1 < NJ) {
            load_jtile(su, buf ^ 1, pix0, b, (j + 1) * TJ, tid);
            CP_COMMIT();
        }

        // ---- S = YKi @ XQj^T, 4-way interleaved accumulators ----
        float S[8][4];
        #pragma unroll
        for (int nt = 0; nt < 8; nt++)
            #pragma unroll
            for (int e = 0; e < 4; e++) S[nt][e] = 0.f;

        #pragma unroll
        for (int kb = 0; kb < 8; kb++) {
            LD_SGROUP(fB, kb, 1);
            S_MMAS(fA, kb, 0);
            if (kb < 7) LD_SGROUP(fA, kb + 1, 0);
            S_MMAS(fB, kb, 1);
        }

        // ---- prime first PV group BEFORE sigmoid (latency hidden by MUFU) ----
        LD_PGROUP(fA, 0, 0);

        // ---- sigmoid (exact: EX2 + RCP) ----
        #pragma unroll
        for (int nt = 0; nt < 8; nt++)
            #pragma unroll
            for (int e = 0; e < 4; e++) {
                float ev = __expf(-S[nt][e]);
                S[nt][e] = __fdividef(1.f, 1.f + ev);
            }

        // ---- pack A-fragments (accumulator layout == A-operand layout) ----
        uint32_t aPh[4][4], aPl[4][4];
        #pragma unroll
        for (int kb = 0; kb < 4; kb++) {
            packHL(S[2*kb  ][0], S[2*kb  ][1], aPh[kb][0], aPl[kb][0]);
            packHL(S[2*kb  ][2], S[2*kb  ][3], aPh[kb][1], aPl[kb][1]);
            packHL(S[2*kb+1][0], S[2*kb+1][1], aPh[kb][2], aPl[kb][2]);
            packHL(S[2*kb+1][2], S[2*kb+1][3], aPh[kb][3], aPl[kb][3]);
        }

        // ---- O += A @ YKj, 4-way interleaved accumulators ----
        #pragma unroll
        for (int g = 0; g < 4; g++) {
            LD_PGROUP(fB, g, 1);
            P_MMAS(fA, g, 0);
            LD_PGROUP(fA, g, 2);
            P_MMAS(fB, g, 1);
            LD_PGROUP(fB, g, 3);
            P_MMAS(fA, g, 2);
            if (g < 3) LD_PGROUP(fA, g + 1, 0);
            P_MMAS(fB, g, 3);
        }
    }

    // ---- epilogue: out = O + XQ (fp32 residual) ----
    const long rowbase = pix0 + i0 + w*16;
    #pragma unroll
    for (int nt = 0; nt < 16; nt++) {
        const int c = 8*nt + 2*qd;
        const long o0 = (rowbase + r0    ) * kC + c;
        const long o1 = (rowbase + r0 + 8) * kC + c;
        float2 q0 = *reinterpret_cast<const float2*>(g_xq + o0);
        float2 q1 = *reinterpret_cast<const float2*>(g_xq + o1);
        *reinterpret_cast<float2*>(out + o0) = make_float2(O[nt][0] + q0.x, O[nt][1] + q0.y);
        *reinterpret_cast<float2*>(out + o1) = make_float2(O[nt][2] + q1.x, O[nt][3] + q1.y);
    }
}

// ---------------------------------------------------------------------------
extern "C" void kernel_launch(void* const* d_in, const int* in_sizes, int n_in,
                              void* d_out, int out_size)
{
    const float* x  = (const float*)d_in[0];
    const float* y  = (const float*)d_in[1];
    const float* W1 = (const float*)d_in[2];
    const float* b1 = (const float*)d_in[3];
    const float* W2 = (const float*)d_in[4];
    const float* b2 = (const float*)d_in[5];

    cudaFuncSetAttribute(attn_mma, cudaFuncAttributeMaxDynamicSharedMemorySize, SMEM_TOTAL);

    proj_kernel<<<dim3(256, 2), 256>>>(x, y, W1, b1, W2, b2);
    attn_mma<<<dim3(32, 4), 256, SMEM_TOTAL>>>((float*)d_out);
}

// round 16
// speedup vs baseline: 1.3760x; 1.1373x over previous
#include <cuda_runtime.h>
#include <cuda_fp16.h>
#include <cstdint>

// ============================================================================
// out = sigmoid(YK @ XQ^T) @ YK + XQ ;  XQ = x@W1+b1, YK = y@W2+b2
// B=4, HW=4096, C=NF=128 fp32.
// R16: fp16 (11-bit mantissa) replaces bf16. S-GEMM: 3-pass hi/lo split
// (err ~1e-6). PV-GEMM: Y as SINGLE fp16 (2^-12 rounding -> ~2.4e-4 out err),
// A split hi/lo -> 2 passes. PV B-bytes + YT smem halve; MMA count -17%.
// Invariant found in R6-R15: SM crossbar bytes serialize with tensor; this
// round cuts bytes and MMAs instead of reordering.
// ============================================================================

constexpr int kB = 4, kHW = 4096, kC = 128;
constexpr int TJ = 64, NJ = kHW / TJ;     // 64-wide j tiles
constexpr int TI = 128;

constexpr int XQ_STR = 68;   // 128 fp16 + 8 pad  (272 B/row), b32 units
constexpr int YT_STR = 36;   // 64 fp16 + 8 pad   (144 B/row)

constexpr int XQH_OFF = 0;                      // 64 x 272 = 17408 B
constexpr int XQL_OFF = 17408;
constexpr int YTH_OFF = 34816;                  // 128 x 144 = 18432 B
constexpr int BUF_BYTES = 53248;
constexpr int SMEM_TOTAL = 2 * BUF_BYTES;       // 106496 B

__device__ float          g_xq  [kB*kHW*kC];
__device__ unsigned short g_xq_h[kB*kHW*kC], g_xq_l[kB*kHW*kC];
__device__ unsigned short g_yk_h[kB*kHW*kC], g_yk_l[kB*kHW*kC];
__device__ unsigned short g_yt_h[kB*kHW*kC];    // [b][feat][pix], fp16 hi only

// ---------------------------------------------------------------------------
__device__ __forceinline__ uint32_t smem_u32(const void* p) {
    uint32_t a;
    asm("{ .reg .u64 t; cvta.to.shared.u64 t, %1; cvt.u32.u64 %0, t; }" : "=r"(a) : "l"(p));
    return a;
}
#define CP16(sm_addr, g_ptr) \
    asm volatile("cp.async.cg.shared.global [%0], [%1], 16;" \
        :: "r"(sm_addr), "l"(__cvta_generic_to_global(g_ptr)) : "memory")
#define CP_COMMIT() asm volatile("cp.async.commit_group;" ::: "memory")
#define CP_WAIT0()  asm volatile("cp.async.wait_group 0;" ::: "memory")

__device__ __forceinline__ void mma_f16(float* d, const uint32_t* a,
                                        uint32_t b0, uint32_t b1) {
    asm volatile(
        "mma.sync.aligned.m16n8k16.row.col.f32.f16.f16.f32 "
        "{%0,%1,%2,%3}, {%4,%5,%6,%7}, {%8,%9}, {%0,%1,%2,%3};"
        : "+f"(d[0]), "+f"(d[1]), "+f"(d[2]), "+f"(d[3])
        : "r"(a[0]), "r"(a[1]), "r"(a[2]), "r"(a[3]), "r"(b0), "r"(b1));
}
__device__ __forceinline__ void packHL(float a0, float a1, uint32_t& hi, uint32_t& lo) {
    __half h0 = __float2half_rn(a0), h1 = __float2half_rn(a1);
    float l0 = a0 - __half2float(h0);
    float l1 = a1 - __half2float(h1);
    __half e0 = __float2half_rn(l0), e1 = __float2half_rn(l1);
    hi = (uint32_t)__half_as_ushort(h0) | ((uint32_t)__half_as_ushort(h1) << 16);
    lo = (uint32_t)__half_as_ushort(e0) | ((uint32_t)__half_as_ushort(e1) << 16);
}

#define LDM4(f, a)                                                             \
    asm volatile("ldmatrix.sync.aligned.m8n8.x4.shared.b16 {%0,%1,%2,%3}, [%4];" \
        : "=r"((f)[0]), "=r"((f)[1]), "=r"((f)[2]), "=r"((f)[3]) : "r"(a))

// ---- S side: identical to R15 (lanes 0-7 hi klo / 8-15 hi khi / 16-23 lo klo
// / 24-31 lo khi; per-lane base sOffL). One LDM4 = {bh0,bh1,bl0,bl1}.
#define LD_SGROUP(f, kb, g) do {                                               \
    LDM4((f)[0], bufS + (uint32_t)((8*((g)*4+0)*XQ_STR + (kb)*8) << 2));       \
    LDM4((f)[1], bufS + (uint32_t)((8*((g)*4+1)*XQ_STR + (kb)*8) << 2));       \
    LDM4((f)[2], bufS + (uint32_t)((8*((g)*4+2)*XQ_STR + (kb)*8) << 2));       \
    LDM4((f)[3], bufS + (uint32_t)((8*((g)*4+3)*XQ_STR + (kb)*8) << 2));       \
} while (0)

#define S_MMAS(f, kb, g) do {                                                  \
    mma_f16(S[(g)*4+0], aH[kb], (f)[0][0], (f)[0][1]);                         \
    mma_f16(S[(g)*4+1], aH[kb], (f)[1][0], (f)[1][1]);                         \
    mma_f16(S[(g)*4+2], aH[kb], (f)[2][0], (f)[2][1]);                         \
    mma_f16(S[(g)*4+3], aH[kb], (f)[3][0], (f)[3][1]);                         \
    mma_f16(S[(g)*4+0], aH[kb], (f)[0][2], (f)[0][3]);                         \
    mma_f16(S[(g)*4+1], aH[kb], (f)[1][2], (f)[1][3]);                         \
    mma_f16(S[(g)*4+2], aH[kb], (f)[2][2], (f)[2][3]);                         \
    mma_f16(S[(g)*4+3], aH[kb], (f)[3][2], (f)[3][3]);                         \
    mma_f16(S[(g)*4+0], aL[kb], (f)[0][0], (f)[0][1]);                         \
    mma_f16(S[(g)*4+1], aL[kb], (f)[1][0], (f)[1][1]);                         \
    mma_f16(S[(g)*4+2], aL[kb], (f)[2][0], (f)[2][1]);                         \
    mma_f16(S[(g)*4+3], aL[kb], (f)[3][0], (f)[3][1]);                         \
} while (0)

// ---- PV side: Y hi only. Lanes 0-7: even nt-group rows k-lo; 8-15: k-hi;
// 16-23: odd nt-group rows k-lo; 24-31: k-hi (per-lane base pOffL).
// One LDM4 covers TWO 8-row nt groups for one 16-wide k-chunk.
#define LD_PG(f, g, kb) do {                                                   \
    LDM4((f)[0], bufP + (uint32_t)((8*((g)*4+0)*YT_STR + (kb)*8) << 2));       \
    LDM4((f)[1], bufP + (uint32_t)((8*((g)*4+2)*YT_STR + (kb)*8) << 2));       \
} while (0)

// 8 MMAs: Ah pass over 4 accumulators, then Al pass (same-acc distance 4)
#define P_MMAS(f, g, kb) do {                                                  \
    mma_f16(O[(g)*4+0], aPh[kb], (f)[0][0], (f)[0][1]);                        \
    mma_f16(O[(g)*4+1], aPh[kb], (f)[0][2], (f)[0][3]);                        \
    mma_f16(O[(g)*4+2], aPh[kb], (f)[1][0], (f)[1][1]);                        \
    mma_f16(O[(g)*4+3], aPh[kb], (f)[1][2], (f)[1][3]);                        \
    mma_f16(O[(g)*4+0], aPl[kb], (f)[0][0], (f)[0][1]);                        \
    mma_f16(O[(g)*4+1], aPl[kb], (f)[0][2], (f)[0][3]);                        \
    mma_f16(O[(g)*4+2], aPl[kb], (f)[1][0], (f)[1][1]);                        \
    mma_f16(O[(g)*4+3], aPl[kb], (f)[1][2], (f)[1][3]);                        \
} while (0)

// ---------------------------------------------------------------------------
// Projection: XQ/YK fp32 + fp16 hi/lo splits + YK^T fp16-hi copy.
// ---------------------------------------------------------------------------
__global__ __launch_bounds__(256) void proj_kernel(
    const float* __restrict__ x,  const float* __restrict__ y,
    const float* __restrict__ W1, const float* __restrict__ b1,
    const float* __restrict__ W2, const float* __restrict__ b2)
{
    __shared__ float  xs[64][129];
    __shared__ float4 ws[16][32];

    const int which = blockIdx.y;
    const float* in   = which ? y  : x;
    const float* W    = which ? W2 : W1;
    const float* bias = which ? b2 : b1;

    const int base = blockIdx.x * 64;
    const int t = threadIdx.x, row = t & 63, fgrp = t >> 6, f0 = fgrp * 32;

    for (int v = t; v < 64*32; v += 256) {
        int r = v >> 5, c4 = v & 31;
        float4 d = reinterpret_cast<const float4*>(in + (long)(base + r)*kC)[c4];
        xs[r][c4*4+0]=d.x; xs[r][c4*4+1]=d.y; xs[r][c4*4+2]=d.z; xs[r][c4*4+3]=d.w;
    }
    float acc[32];
    #pragma unroll
    for (int i = 0; i < 32; i++) acc[i] = bias[f0 + i];

    for (int c0 = 0; c0 < kC; c0 += 16) {
        __syncthreads();
        for (int v = t; v < 16*32; v += 256) {
            int r = v >> 5, c4 = v & 31;
            ws[r][c4] = reinterpret_cast<const float4*>(W + (long)(c0 + r)*kC)[c4];
        }
        __syncthreads();
        #pragma unroll
        for (int cc = 0; cc < 16; cc++) {
            float xv = xs[row][c0 + cc];
            #pragma unroll
            for (int q = 0; q < 8; q++) {
                float4 w = ws[cc][fgrp*8 + q];
                acc[q*4+0] += xv*w.x; acc[q*4+1] += xv*w.y;
                acc[q*4+2] += xv*w.z; acc[q*4+3] += xv*w.w;
            }
        }
    }

    const int prow = base + row;
    unsigned short hs[32], ls[32];
    #pragma unroll
    for (int i = 0; i < 32; i++) {
        float v = acc[i];
        __half h = __float2half_rn(v);
        float lf = v - __half2float(h);
        hs[i] = __half_as_ushort(h);
        ls[i] = __half_as_ushort(__float2half_rn(lf));
    }
    unsigned hw_[16], lw_[16];
    #pragma unroll
    for (int k = 0; k < 16; k++) {
        hw_[k] = (unsigned)hs[2*k] | ((unsigned)hs[2*k+1] << 16);
        lw_[k] = (unsigned)ls[2*k] | ((unsigned)ls[2*k+1] << 16);
    }
    const int u4base = prow * 16 + fgrp * 4;

    if (which == 0) {
        float* o = g_xq + (long)prow*kC + f0;
        #pragma unroll
        for (int q = 0; q < 8; q++)
            reinterpret_cast<float4*>(o)[q] =
                make_float4(acc[q*4+0], acc[q*4+1], acc[q*4+2], acc[q*4+3]);
        #pragma unroll
        for (int q = 0; q < 4; q++) {
            reinterpret_cast<uint4*>(g_xq_h)[u4base+q] = make_uint4(hw_[4*q],hw_[4*q+1],hw_[4*q+2],hw_[4*q+3]);
            reinterpret_cast<uint4*>(g_xq_l)[u4base+q] = make_uint4(lw_[4*q],lw_[4*q+1],lw_[4*q+2],lw_[4*q+3]);
        }
    } else {
        #pragma unroll
        for (int q = 0; q < 4; q++) {
            reinterpret_cast<uint4*>(g_yk_h)[u4base+q] = make_uint4(hw_[4*q],hw_[4*q+1],hw_[4*q+2],hw_[4*q+3]);
            reinterpret_cast<uint4*>(g_yk_l)[u4base+q] = make_uint4(lw_[4*q],lw_[4*q+1],lw_[4*q+2],lw_[4*q+3]);
        }
        const int bb = prow >> 12, pb = prow & 4095;
        #pragma unroll
        for (int i = 0; i < 32; i++) {            // coalesced: lanes = consecutive pb
            g_yt_h[(bb*kC + f0 + i)*kHW + pb] = hs[i];
        }
    }
}

// ---------------------------------------------------------------------------
// j-tile loader: XQ hi/lo [64 x 128] + YT hi [128 x 64] via cp.async (256 thr)
// ---------------------------------------------------------------------------
__device__ __forceinline__ void load_jtile(uint32_t su, int buf, long pix0,
                                           int bIdx, int j0, int tid) {
    const uint32_t base = su + buf * BUF_BYTES;
    #pragma unroll
    for (int k = 0; k < 4; k++) {                 // XQ: 1024 chunks each
        int idx = tid + k*256, row = idx >> 4, q = idx & 15;
        CP16(base + XQH_OFF + row*272 + q*16, g_xq_h + (pix0 + j0 + row)*kC + q*8);
        CP16(base + XQL_OFF + row*272 + q*16, g_xq_l + (pix0 + j0 + row)*kC + q*8);
    }
    const long ytb = (long)bIdx * kC * kHW + j0;
    #pragma unroll
    for (int k = 0; k < 4; k++) {                 // YT hi: 1024 chunks
        int idx = tid + k*256, row = idx >> 3, q = idx & 7;
        CP16(base + YTH_OFF + row*144 + q*16, g_yt_h + ytb + (long)row*kHW + q*8);
    }
}

// ---------------------------------------------------------------------------
// Attention: grid (32 i-tiles, 4 batches), block 256 (8 warps x 16 rows)
// ---------------------------------------------------------------------------
__global__ __launch_bounds__(256) void attn_mma(float* __restrict__ out)
{
    extern __shared__ char smem[];
    const uint32_t su = smem_u32(smem);
    const int tid = threadIdx.x, w = tid >> 5, lane = tid & 31;
    const int r0 = lane >> 2, qd = lane & 3;
    const int b = blockIdx.y, i0 = blockIdx.x * TI;
    const long pix0 = (long)b * kHW;

    // per-lane ldmatrix base offsets (bytes, within a buffer)
    const int li8 = lane & 7, seg = (lane >> 3) & 1;
    const int hlo = lane >> 4;                    // S: hi vs lo buffer
    const uint32_t sOffL = (uint32_t)(hlo ? XQL_OFF : XQH_OFF)
                         + ((uint32_t)(li8*XQ_STR + seg*4) << 2);
    const int gsel = lane >> 4;                   // PV: even vs odd nt-group
    const uint32_t pOffL = (uint32_t)YTH_OFF
                         + ((uint32_t)((gsel*8 + li8)*YT_STR + seg*4) << 2);

    load_jtile(su, 0, pix0, b, 0, tid);
    CP_COMMIT();

    // YKi hi AND lo A-fragments resident (one-time gmem loads)
    uint32_t aH[8][4], aL[8][4];
    const unsigned short* ykbh = g_yk_h + (pix0 + i0 + w*16) * kC;
    const unsigned short* ykbl = g_yk_l + (pix0 + i0 + w*16) * kC;
    #pragma unroll
    for (int kb = 0; kb < 8; kb++) {
        int c0 = kb*16 + 2*qd;
        aH[kb][0] = *reinterpret_cast<const uint32_t*>(ykbh +  r0      *kC + c0);
        aH[kb][1] = *reinterpret_cast<const uint32_t*>(ykbh + (r0 + 8) *kC + c0);
        aH[kb][2] = *reinterpret_cast<const uint32_t*>(ykbh +  r0      *kC + c0 + 8);
        aH[kb][3] = *reinterpret_cast<const uint32_t*>(ykbh + (r0 + 8) *kC + c0 + 8);
        aL[kb][0] = *reinterpret_cast<const uint32_t*>(ykbl +  r0      *kC + c0);
        aL[kb][1] = *reinterpret_cast<const uint32_t*>(ykbl + (r0 + 8) *kC + c0);
        aL[kb][2] = *reinterpret_cast<const uint32_t*>(ykbl +  r0      *kC + c0 + 8);
        aL[kb][3] = *reinterpret_cast<const uint32_t*>(ykbl + (r0 + 8) *kC + c0 + 8);
    }

    float O[16][4];
    #pragma unroll
    for (int nt = 0; nt < 16; nt++)
        #pragma unroll
        for (int e = 0; e < 4; e++) O[nt][e] = 0.f;

    for (int j = 0; j < NJ; j++) {
        const int buf = j & 1;
        CP_WAIT0();
        __syncthreads();

        const uint32_t bufbyte = su + (uint32_t)(buf * BUF_BYTES);
        const uint32_t bufS = bufbyte + sOffL;
        const uint32_t bufP = bufbyte + pOffL;

        uint32_t fA[4][4], fB[4][4];
        LD_SGROUP(fA, 0, 0);      // prime ahead of the cp.async burst

        if (j + 1 < NJ) {
            load_jtile(su, buf ^ 1, pix0, b, (j + 1) * TJ, tid);
            CP_COMMIT();
        }

        // ---- S = YKi @ XQj^T (fp16 hh+hl+lh), 4-way interleaved accums ----
        float S[8][4];
        #pragma unroll
        for (int nt = 0; nt < 8; nt++)
            #pragma unroll
            for (int e = 0; e < 4; e++) S[nt][e] = 0.f;

        #pragma unroll
        for (int kb = 0; kb < 8; kb++) {
            LD_SGROUP(fB, kb, 1);
            S_MMAS(fA, kb, 0);
            if (kb < 7) LD_SGROUP(fA, kb + 1, 0);
            S_MMAS(fB, kb, 1);
        }

        // ---- prime first PV fragments BEFORE sigmoid ----
        uint32_t pA[2][4], pB[2][4];
        LD_PG(pA, 0, 0);

        // ---- sigmoid (exact: EX2 + RCP) ----
        #pragma unroll
        for (int nt = 0; nt < 8; nt++)
            #pragma unroll
            for (int e = 0; e < 4; e++) {
                float ev = __expf(-S[nt][e]);
                S[nt][e] = __fdividef(1.f, 1.f + ev);
            }

        // ---- pack A-fragments, fp16 hi/lo (acc layout == A-operand layout) ----
        uint32_t aPh[4][4], aPl[4][4];
        #pragma unroll
        for (int kb = 0; kb < 4; kb++) {
            packHL(S[2*kb  ][0], S[2*kb  ][1], aPh[kb][0], aPl[kb][0]);
            packHL(S[2*kb  ][2], S[2*kb  ][3], aPh[kb][1], aPl[kb][1]);
            packHL(S[2*kb+1][0], S[2*kb+1][1], aPh[kb][2], aPl[kb][2]);
            packHL(S[2*kb+1][2], S[2*kb+1][3], aPh[kb][3], aPl[kb][3]);
        }

        // ---- O += A @ YKj (Ah·Yh + Al·Yh), double-buffered fragments ----
        #pragma unroll
        for (int g = 0; g < 4; g++) {
            LD_PG(pB, g, 1);
            P_MMAS(pA, g, 0);
            LD_PG(pA, g, 2);
            P_MMAS(pB, g, 1);
            LD_PG(pB, g, 3);
            P_MMAS(pA, g, 2);
            if (g < 3) LD_PG(pA, g + 1, 0);
            P_MMAS(pB, g, 3);
        }
    }

    // ---- epilogue: out = O + XQ (fp32 residual) ----
    const long rowbase = pix0 + i0 + w*16;
    #pragma unroll
    for (int nt = 0; nt < 16; nt++) {
        const int c = 8*nt + 2*qd;
        const long o0 = (rowbase + r0    ) * kC + c;
        const long o1 = (rowbase + r0 + 8) * kC + c;
        float2 q0 = *reinterpret_cast<const float2*>(g_xq + o0);
        float2 q1 = *reinterpret_cast<const float2*>(g_xq + o1);
        *reinterpret_cast<float2*>(out + o0) = make_float2(O[nt][0] + q0.x, O[nt][1] + q0.y);
        *reinterpret_cast<float2*>(out + o1) = make_float2(O[nt][2] + q1.x, O[nt][3] + q1.y);
    }
}

// ---------------------------------------------------------------------------
extern "C" void kernel_launch(void* const* d_in, const int* in_sizes, int n_in,
                              void* d_out, int out_size)
{
    const float* x  = (const float*)d_in[0];
    const float* y  = (const float*)d_in[1];
    const float* W1 = (const float*)d_in[2];
    const float* b1 = (const float*)d_in[3];
    const float* W2 = (const float*)d_in[4];
    const float* b2 = (const float*)d_in[5];

    cudaFuncSetAttribute(attn_mma, cudaFuncAttributeMaxDynamicSharedMemorySize, SMEM_TOTAL);

    proj_kernel<<<dim3(256, 2), 256>>>(x, y, W1, b1, W2, b2);
    attn_mma<<<dim3(32, 4), 256, SMEM_TOTAL>>>((float*)d_out);
}